// round 13
// baseline (speedup 1.0000x reference)
#include <cuda_runtime.h>
#include <cuda_fp16.h>
#include <math.h>
#include <stdint.h>

#define BB   4
#define LL   4096
#define DD   1024
#define HH   16
#define DHH  64
#define MMF  256
#define DFF  4096
#define NT   (BB*LL)      /* 16384 tokens  */
#define NR   (NT*HH)      /* 262144 (t,h) rows */
#define KVN  (BB*HH*MMF*DHH)   /* 1048576 */

// ---------------- scratch (device globals; no allocation allowed) ----------
__device__ float  g_kvp  [4*KVN];
__device__ float  g_ksum [BB*HH*MMF];
__device__ float  g_den  [NR];
__device__ float  g_tmp  [(size_t)NT*DD];
__device__ float  g_out1 [(size_t)NT*DD];
__device__ unsigned g_kmax;
// fp16 buffers
__device__ __half g_xh   [(size_t)NT*DD];
__device__ __half g_qh   [(size_t)NT*DD];
__device__ __half g_kh   [(size_t)NT*DD];
__device__ __half g_vh   [(size_t)NT*DD];
__device__ __half g_qph  [(size_t)NR*MMF];
__device__ __half g_kph  [(size_t)NR*MMF];
__device__ __half g_kvh  [KVN];
__device__ __half g_out1h[(size_t)NT*DD];
__device__ __half g_attnh[(size_t)NT*DD];
__device__ __half g_hh   [(size_t)NT*DFF];
__device__ __half g_projh[MMF*DHH];
__device__ __half g_wqkvT[3*DD*DD];             // packed [3072][1024]
__device__ __half g_woT  [DD*DD];
__device__ __half g_w1T  [(size_t)DFF*DD];
__device__ __half g_w2T  [(size_t)DD*DFF];

enum { EPI_NONE = 0, EPI_BIAS = 1, EPI_BIAS_ELU = 2 };
enum { DD_Q = 0, DD_KMAX = 1, DD_KEXP = 2 };

// ---------------- helpers ----------------------------------------------------
__device__ __forceinline__ void mma_f16(float* d, const unsigned* a,
                                        const unsigned* b)
{
    asm volatile(
        "mma.sync.aligned.m16n8k16.row.col.f32.f16.f16.f32 "
        "{%0,%1,%2,%3}, {%4,%5,%6,%7}, {%8,%9}, {%0,%1,%2,%3};\n"
        : "+f"(d[0]), "+f"(d[1]), "+f"(d[2]), "+f"(d[3])
        : "r"(a[0]), "r"(a[1]), "r"(a[2]), "r"(a[3]),
          "r"(b[0]), "r"(b[1]));
}

__device__ __forceinline__ void ldsm_x4(unsigned* r, unsigned addr)
{
    asm volatile("ldmatrix.sync.aligned.m8n8.x4.shared.b16 {%0,%1,%2,%3}, [%4];"
        : "=r"(r[0]), "=r"(r[1]), "=r"(r[2]), "=r"(r[3]) : "r"(addr));
}

__device__ __forceinline__ void ldsm_x4t(unsigned* r, unsigned addr)
{
    asm volatile("ldmatrix.sync.aligned.m8n8.x4.trans.shared.b16 {%0,%1,%2,%3}, [%4];"
        : "=r"(r[0]), "=r"(r[1]), "=r"(r[2]), "=r"(r[3]) : "r"(addr));
}

__device__ __forceinline__ float unflip(unsigned u)
{
    return __uint_as_float((u & 0x80000000u) ? (u ^ 0x80000000u) : ~u);
}

__device__ __forceinline__ __half2 h2ex2(__half2 x)
{
    unsigned u = *(unsigned*)&x, y;
    asm("ex2.approx.f16x2 %0, %1;" : "=r"(y) : "r"(u));
    return *(__half2*)&y;
}

// ------- fp16 GEMM, CTA tile 128x256, 512 threads = 16 warps (4m x 4n), ------
// warp tile 32x64 (proven mapping), BK=32, double-buffered, one sync/iter.
// A [M][K], B [N][K]. SPLIT3: route each 1024-col slice of N to C/C2/C3.
#define HS 40
#define ABUF (128 * HS)                 /* halves per A buffer */
#define BBUF (256 * HS)                 /* halves per B buffer */

template<int EPI, typename OutT, bool SPLIT3>
__global__ __launch_bounds__(512, 1)
void hgemm512(const __half* __restrict__ A, const __half* __restrict__ B,
              const float* __restrict__ bias, OutT* __restrict__ C,
              __half* __restrict__ C2, __half* __restrict__ C3,
              int M, int N, int K)
{
    __shared__ __align__(16) __half As[2 * ABUF];
    __shared__ __align__(16) __half Bs[2 * BBUF];

    const int tid  = threadIdx.x;
    const int wid  = tid >> 5;
    const int lane = tid & 31;
    const int wm   = (wid >> 2) * 32;
    const int wn   = (wid & 3)  * 64;
    const size_t m0 = (size_t)blockIdx.y * 128;
    const int    n0 = blockIdx.x * 256;

    // staging: A 128x32 = 512 uint4 (1/thread); B 256x32 = 1024 uint4 (2/thread)
    const int ar = tid >> 2, aq = (tid & 3) << 3;
    const int br0 = tid >> 2, br1 = br0 + 128;

    const int matid = lane >> 3, rowin = lane & 7;
    const unsigned sAb = (unsigned)__cvta_generic_to_shared(As);
    const unsigned sBb = (unsigned)__cvta_generic_to_shared(Bs);
    unsigned aoff[2], boff[4];
#pragma unroll
    for (int mt = 0; mt < 2; mt++)
        aoff[mt] = sAb + (unsigned)(((wm + mt * 16 + rowin + ((matid & 1) << 3)) * HS
                                     + ((matid & 2) << 2)) << 1);
#pragma unroll
    for (int p = 0; p < 4; p++)
        boff[p] = sBb + (unsigned)(((wn + ((p << 1) + ((matid >> 1) & 1)) * 8 + rowin) * HS
                                     + ((matid & 1) << 3)) << 1);

    uint4 ra, rb0, rb1;
    float acc[2][8][4];
#pragma unroll
    for (int mt = 0; mt < 2; mt++)
#pragma unroll
        for (int nt = 0; nt < 8; nt++)
#pragma unroll
            for (int i = 0; i < 4; i++) acc[mt][nt][i] = 0.f;

    const int iters = K >> 5;

    // prologue
    ra  = *(const uint4*)(A + (m0 + ar) * K + aq);
    rb0 = *(const uint4*)(B + (size_t)(n0 + br0) * K + aq);
    rb1 = *(const uint4*)(B + (size_t)(n0 + br1) * K + aq);
    *(uint4*)&As[ar * HS + aq]  = ra;
    *(uint4*)&Bs[br0 * HS + aq] = rb0;
    *(uint4*)&Bs[br1 * HS + aq] = rb1;
    __syncthreads();

    for (int it = 0; it < iters; it++) {
        const bool more = (it + 1 < iters);
        if (more) {
            int k0 = (it + 1) << 5;
            ra  = *(const uint4*)(A + (m0 + ar) * K + k0 + aq);
            rb0 = *(const uint4*)(B + (size_t)(n0 + br0) * K + k0 + aq);
            rb1 = *(const uint4*)(B + (size_t)(n0 + br1) * K + k0 + aq);
        }

        const unsigned ab = (unsigned)((it & 1) * (ABUF * 2));
        const unsigned bb = (unsigned)((it & 1) * (BBUF * 2));
#pragma unroll
        for (int ks = 0; ks < 2; ks++) {
            const unsigned cb = (unsigned)(ks << 5);
            unsigned af[2][4], bf[4][4];
#pragma unroll
            for (int mt = 0; mt < 2; mt++) ldsm_x4(af[mt], aoff[mt] + ab + cb);
#pragma unroll
            for (int p = 0; p < 4; p++)   ldsm_x4(bf[p],  boff[p]  + bb + cb);
#pragma unroll
            for (int mt = 0; mt < 2; mt++)
#pragma unroll
                for (int p = 0; p < 4; p++) {
                    mma_f16(acc[mt][2 * p],     af[mt], &bf[p][0]);
                    mma_f16(acc[mt][2 * p + 1], af[mt], &bf[p][2]);
                }
        }

        if (more) {
            const int s = ((it + 1) & 1);
            *(uint4*)&As[s * ABUF + ar * HS + aq]  = ra;
            *(uint4*)&Bs[s * BBUF + br0 * HS + aq] = rb0;
            *(uint4*)&Bs[s * BBUF + br1 * HS + aq] = rb1;
        }
        __syncthreads();
    }

    // output routing (SPLIT3: whole CTA stays in one 1024-col slice)
    __half* Ch = nullptr;
    int nbase = n0;
    if (SPLIT3) {
        const int slice = n0 >> 10;
        Ch = (slice == 0) ? (__half*)C : ((slice == 1) ? C2 : C3);
        nbase = n0 & 1023;
    }
    const int NN = SPLIT3 ? 1024 : N;

#pragma unroll
    for (int mt = 0; mt < 2; mt++) {
#pragma unroll
        for (int nt = 0; nt < 8; nt++) {
            size_t row = m0 + wm + mt * 16 + (lane >> 2);
            int col = nbase + wn + nt * 8 + ((lane & 3) << 1);
            float2 lo = make_float2(acc[mt][nt][0], acc[mt][nt][1]);
            float2 hi = make_float2(acc[mt][nt][2], acc[mt][nt][3]);
            if (EPI == EPI_BIAS || EPI == EPI_BIAS_ELU) {
                float2 bb2 = *(const float2*)(bias + (n0 + wn + nt * 8 + ((lane & 3) << 1)));
                lo.x += bb2.x; lo.y += bb2.y;
                hi.x += bb2.x; hi.y += bb2.y;
            }
            if (EPI == EPI_BIAS_ELU) {
                lo.x = lo.x > 0.f ? lo.x : expm1f(lo.x);
                lo.y = lo.y > 0.f ? lo.y : expm1f(lo.y);
                hi.x = hi.x > 0.f ? hi.x : expm1f(hi.x);
                hi.y = hi.y > 0.f ? hi.y : expm1f(hi.y);
            }
            if (SPLIT3) {
                *(__half2*)(Ch + row * 1024 + col)       = __floats2half2_rn(lo.x, lo.y);
                *(__half2*)(Ch + (row + 8) * 1024 + col) = __floats2half2_rn(hi.x, hi.y);
            } else if (sizeof(OutT) == 2) {
                *(__half2*)((__half*)C + row * NN + col)       = __floats2half2_rn(lo.x, lo.y);
                *(__half2*)((__half*)C + (row + 8) * NN + col) = __floats2half2_rn(hi.x, hi.y);
            } else {
                *(float2*)((float*)C + row * NN + col)       = lo;
                *(float2*)((float*)C + (row + 8) * NN + col) = hi;
            }
        }
    }
}

// ---------------- fused dd GEMM + Performer feature map -----------------------
// (unchanged from R12 — proven)
#define DS 72

template<int MODE>
__global__ __launch_bounds__(256, 2)
void ddexp(const __half* __restrict__ A, const __half* __restrict__ Bp,
           __half* __restrict__ outp, unsigned* __restrict__ gmax)
{
    __shared__ __align__(16) __half As[64 * DS];
    __shared__ __align__(16) __half Bs[256 * DS];
    __shared__ float sdiag[64];
    __shared__ float srmax[4][64];

    const int tid  = threadIdx.x;
    const int wid  = tid >> 5;
    const int lane = tid & 31;
    const int wm   = (wid >> 2) * 32;
    const int wn   = (wid & 3)  * 64;
    const size_t m0 = (size_t)blockIdx.x * 64;

#pragma unroll
    for (int i = 0; i < 2; i++) {
        int c = tid + i * 256;
        int r = c >> 3, cc = (c & 7) << 3;
        *(uint4*)&As[r * DS + cc] = *(const uint4*)(A + (m0 + r) * 64 + cc);
    }
#pragma unroll
    for (int i = 0; i < 8; i++) {
        int c = tid + i * 256;
        int r = c >> 3, cc = (c & 7) << 3;
        *(uint4*)&Bs[r * DS + cc] = *(const uint4*)(Bp + (size_t)r * 64 + cc);
    }
    __syncthreads();

    if (MODE != DD_KMAX && tid < 64) {
        const __half2* row = (const __half2*)&As[tid * DS];
        float ss = 0.f;
#pragma unroll
        for (int i = 0; i < 32; i++) {
            float2 v = __half22float2(row[i]);
            ss += v.x * v.x + v.y * v.y;
        }
        sdiag[tid] = ss;
    }

    const int matid = lane >> 3, rowin = lane & 7;
    const unsigned sA = (unsigned)__cvta_generic_to_shared(As);
    const unsigned sB = (unsigned)__cvta_generic_to_shared(Bs);
    unsigned aoff[2], boff[4];
#pragma unroll
    for (int mt = 0; mt < 2; mt++)
        aoff[mt] = sA + (unsigned)(((wm + mt * 16 + rowin + ((matid & 1) << 3)) * DS
                                    + ((matid & 2) << 2)) << 1);
#pragma unroll
    for (int p = 0; p < 4; p++)
        boff[p] = sB + (unsigned)(((wn + ((p << 1) + ((matid >> 1) & 1)) * 8 + rowin) * DS
                                    + ((matid & 1) << 3)) << 1);

    float acc[2][8][4];
#pragma unroll
    for (int mt = 0; mt < 2; mt++)
#pragma unroll
        for (int nt = 0; nt < 8; nt++)
#pragma unroll
            for (int i = 0; i < 4; i++) acc[mt][nt][i] = 0.f;

#pragma unroll
    for (int ks = 0; ks < 4; ks++) {
        const unsigned cb = (unsigned)(ks << 5);
        unsigned af[2][4], bf[4][4];
#pragma unroll
        for (int mt = 0; mt < 2; mt++) ldsm_x4(af[mt], aoff[mt] + cb);
#pragma unroll
        for (int p = 0; p < 4; p++)   ldsm_x4(bf[p],  boff[p]  + cb);
#pragma unroll
        for (int mt = 0; mt < 2; mt++)
#pragma unroll
            for (int p = 0; p < 4; p++) {
                mma_f16(acc[mt][2 * p],     af[mt], &bf[p][0]);
                mma_f16(acc[mt][2 * p + 1], af[mt], &bf[p][2]);
            }
    }

    if (MODE == DD_KMAX) {
        float mx = -3.4e38f;
#pragma unroll
        for (int mt = 0; mt < 2; mt++)
#pragma unroll
            for (int nt = 0; nt < 8; nt++)
#pragma unroll
                for (int i = 0; i < 4; i++) mx = fmaxf(mx, acc[mt][nt][i]);
#pragma unroll
        for (int o = 16; o; o >>= 1) mx = fmaxf(mx, __shfl_xor_sync(0xffffffffu, mx, o));
        if (lane == 0) {
            unsigned u = __float_as_uint(mx);
            u = (u & 0x80000000u) ? ~u : (u | 0x80000000u);
            atomicMax(gmax, u);
        }
        return;
    }

    if (MODE == DD_Q) {
#pragma unroll
        for (int mt = 0; mt < 2; mt++) {
            float m0v = -3.4e38f, m1v = -3.4e38f;
#pragma unroll
            for (int nt = 0; nt < 8; nt++) {
                m0v = fmaxf(m0v, fmaxf(acc[mt][nt][0], acc[mt][nt][1]));
                m1v = fmaxf(m1v, fmaxf(acc[mt][nt][2], acc[mt][nt][3]));
            }
#pragma unroll
            for (int o = 1; o <= 2; o <<= 1) {
                m0v = fmaxf(m0v, __shfl_xor_sync(0xffffffffu, m0v, o));
                m1v = fmaxf(m1v, __shfl_xor_sync(0xffffffffu, m1v, o));
            }
            if ((lane & 3) == 0) {
                srmax[wid & 3][wm + mt * 16 + (lane >> 2)]     = m0v;
                srmax[wid & 3][wm + mt * 16 + 8 + (lane >> 2)] = m1v;
            }
        }
    }
    __syncthreads();

    const float gm = (MODE == DD_KEXP) ? unflip(*gmax) : 0.f;
    const float L2E = 1.4426950408889634f;
    const __half2 eps2 = __float2half2_rn(1e-6f);
    const __half2 rat2 = __float2half2_rn(0.0625f);

#pragma unroll
    for (int mt = 0; mt < 2; mt++) {
        const int r0 = wm + mt * 16 + (lane >> 2);
        const int r1 = r0 + 8;
        float c0, c1;
        if (MODE == DD_Q) {
            float rm0 = fmaxf(fmaxf(srmax[0][r0], srmax[1][r0]),
                              fmaxf(srmax[2][r0], srmax[3][r0]));
            float rm1 = fmaxf(fmaxf(srmax[0][r1], srmax[1][r1]),
                              fmaxf(srmax[2][r1], srmax[3][r1]));
            c0 = 0.0625f * sdiag[r0] + rm0;
            c1 = 0.0625f * sdiag[r1] + rm1;
        } else {
            c0 = 0.0625f * sdiag[r0] + gm;
            c1 = 0.0625f * sdiag[r1] + gm;
        }
        const float c0l = c0 * L2E, c1l = c1 * L2E;
#pragma unroll
        for (int nt = 0; nt < 8; nt++) {
            const int col = wn + nt * 8 + ((lane & 3) << 1);
            __half2 t01 = __floats2half2_rn(fmaf(acc[mt][nt][0], L2E, -c0l),
                                            fmaf(acc[mt][nt][1], L2E, -c0l));
            __half2 t23 = __floats2half2_rn(fmaf(acc[mt][nt][2], L2E, -c1l),
                                            fmaf(acc[mt][nt][3], L2E, -c1l));
            __half2 e01 = __hmul2(__hadd2(h2ex2(t01), eps2), rat2);
            __half2 e23 = __hmul2(__hadd2(h2ex2(t23), eps2), rat2);
            *(__half2*)(outp + (m0 + r0) * 256 + col) = e01;
            *(__half2*)(outp + (m0 + r1) * 256 + col) = e23;
        }
    }
}

// ------------- fp16 batched strided GEMM over (b,h), optional split-K --------
// (unchanged — proven)
#define BAS 136
#define NAS 40
#define BBS 72

template<bool TRANSA, bool DIV, typename OutT, int NSPLIT>
__global__ __launch_bounds__(256, 2)
void hgemm_bh(const __half* __restrict__ A, size_t sAb, size_t sAh, int lda,
              const __half* __restrict__ B, size_t sBb, size_t sBh, int ldb,
              OutT* __restrict__ C, size_t sCb, size_t sCh, int ldc, size_t sCsplit,
              const float* __restrict__ aux, size_t sXb, size_t sXh, int ldx,
              int M, int N, int K)
{
    constexpr int ABUFH = TRANSA ? (32 * BAS) : (128 * NAS);
    constexpr int BBUFH = 32 * BBS;
    __shared__ __align__(16) __half As[2 * ABUFH];
    __shared__ __align__(16) __half Bs[2 * BBUFH];

    const int z     = blockIdx.z;
    const int split = (NSPLIT > 1) ? (z >> 6) : 0;
    const int zz    = (NSPLIT > 1) ? (z & 63) : z;
    const int zb = zz >> 4, zh = zz & 15;
    const __half* Ab = A + (size_t)zb * sAb + (size_t)zh * sAh;
    const __half* Bb = B + (size_t)zb * sBb + (size_t)zh * sBh;
    OutT*         Cb = C + (size_t)zb * sCb + (size_t)zh * sCh
                         + (size_t)split * sCsplit;
    if (NSPLIT > 1) {
        Ab += (size_t)split * K * lda;
        Bb += (size_t)split * K * ldb;
    }

    const int tid  = threadIdx.x;
    const int wid  = tid >> 5;
    const int lane = tid & 31;
    const int wm   = (wid >> 1) * 32;
    const int wn   = (wid & 1)  * 32;
    const int m0   = blockIdx.y * 128;

    const int matid = lane >> 3, rowin = lane & 7;
    const unsigned sAs = (unsigned)__cvta_generic_to_shared(As);
    const unsigned sBs = (unsigned)__cvta_generic_to_shared(Bs);

    unsigned aoff[2], boff[2];
#pragma unroll
    for (int mt = 0; mt < 2; mt++) {
        if (TRANSA)
            aoff[mt] = sAs + (unsigned)(((rowin + ((matid >> 1) << 3)) * BAS
                                         + wm + mt * 16 + ((matid & 1) << 3)) << 1);
        else
            aoff[mt] = sAs + (unsigned)(((wm + mt * 16 + rowin + ((matid & 1) << 3)) * NAS
                                         + ((matid & 2) << 2)) << 1);
    }
#pragma unroll
    for (int p = 0; p < 2; p++)
        boff[p] = sBs + (unsigned)(((rowin + ((matid & 1) << 3)) * BBS
                                    + wn + (p << 4) + ((matid >> 1) << 3)) << 1);

    const int ta_kr = tid >> 4, ta_mc = (tid & 15) << 3;
    const int na_r0 = tid >> 2, na_k0 = (tid & 3) << 3;
    const int b_kr  = tid >> 3, b_nc  = (tid & 7) << 3;

    uint4 ra0, ra1, rb;
    float acc[2][4][4];
#pragma unroll
    for (int mt = 0; mt < 2; mt++)
#pragma unroll
        for (int nt = 0; nt < 4; nt++)
#pragma unroll
            for (int i = 0; i < 4; i++) acc[mt][nt][i] = 0.f;

    const int iters = K >> 5;

    auto ld = [&](int k0) {
        if (TRANSA) {
            ra0 = *(const uint4*)(Ab + (size_t)(k0 + ta_kr)      * lda + m0 + ta_mc);
            ra1 = *(const uint4*)(Ab + (size_t)(k0 + ta_kr + 16) * lda + m0 + ta_mc);
        } else {
            ra0 = *(const uint4*)(Ab + (size_t)(m0 + na_r0)      * lda + k0 + na_k0);
            ra1 = *(const uint4*)(Ab + (size_t)(m0 + na_r0 + 64) * lda + k0 + na_k0);
        }
        rb = *(const uint4*)(Bb + (size_t)(k0 + b_kr) * ldb + b_nc);
    };
    auto st = [&](int s) {
        __half* as = As + s * ABUFH;
        __half* bs = Bs + s * BBUFH;
        if (TRANSA) {
            *(uint4*)&as[ta_kr * BAS + ta_mc]        = ra0;
            *(uint4*)&as[(ta_kr + 16) * BAS + ta_mc] = ra1;
        } else {
            *(uint4*)&as[na_r0 * NAS + na_k0]        = ra0;
            *(uint4*)&as[(na_r0 + 64) * NAS + na_k0] = ra1;
        }
        *(uint4*)&bs[b_kr * BBS + b_nc] = rb;
    };

    ld(0); st(0);
    __syncthreads();

    for (int it = 0; it < iters; it++) {
        const bool more = (it + 1 < iters);
        if (more) ld((it + 1) << 5);

        const unsigned ab = (unsigned)((it & 1) * (ABUFH * 2));
        const unsigned bb = (unsigned)((it & 1) * (BBUFH * 2));
#pragma unroll
        for (int ks = 0; ks < 2; ks++) {
            const unsigned aks = TRANSA ? (unsigned)(ks * 16 * BAS * 2) : (unsigned)(ks << 5);
            const unsigned bks = (unsigned)(ks * 16 * BBS * 2);
            unsigned af[2][4], bf[2][4];
#pragma unroll
            for (int mt = 0; mt < 2; mt++) {
                if (TRANSA) ldsm_x4t(af[mt], aoff[mt] + ab + aks);
                else        ldsm_x4 (af[mt], aoff[mt] + ab + aks);
            }
#pragma unroll
            for (int p = 0; p < 2; p++) ldsm_x4t(bf[p], boff[p] + bb + bks);
#pragma unroll
            for (int mt = 0; mt < 2; mt++)
#pragma unroll
                for (int p = 0; p < 2; p++) {
                    mma_f16(acc[mt][2 * p],     af[mt], &bf[p][0]);
                    mma_f16(acc[mt][2 * p + 1], af[mt], &bf[p][2]);
                }
        }

        if (more) st((it + 1) & 1);
        __syncthreads();
    }

#pragma unroll
    for (int mt = 0; mt < 2; mt++) {
        int row = m0 + wm + mt * 16 + (lane >> 2);
        float dv0 = 1.f, dv1 = 1.f;
        if (DIV) {
            dv0 = 1.f / aux[(size_t)zb * sXb + (size_t)zh * sXh + (size_t)row * ldx];
            dv1 = 1.f / aux[(size_t)zb * sXb + (size_t)zh * sXh + (size_t)(row + 8) * ldx];
        }
#pragma unroll
        for (int nt = 0; nt < 4; nt++) {
            int col = wn + nt * 8 + ((lane & 3) << 1);
            float2 lo = make_float2(acc[mt][nt][0] * dv0, acc[mt][nt][1] * dv0);
            float2 hi = make_float2(acc[mt][nt][2] * dv1, acc[mt][nt][3] * dv1);
            if (sizeof(OutT) == 2) {
                *(__half2*)((__half*)Cb + (size_t)row * ldc + col)       = __floats2half2_rn(lo.x, lo.y);
                *(__half2*)((__half*)Cb + (size_t)(row + 8) * ldc + col) = __floats2half2_rn(hi.x, hi.y);
            } else {
                *(float2*)((float*)Cb + (size_t)row * ldc + col)       = lo;
                *(float2*)((float*)Cb + (size_t)(row + 8) * ldc + col) = hi;
            }
        }
    }
}

// ---------------- small helper kernels --------------------------------------
__global__ void k_half4(const float4* __restrict__ in, __half2* __restrict__ out,
                        int n4)
{
    int i = blockIdx.x * 256 + threadIdx.x;
    if (i < n4) {
        float4 v = in[i];
        out[2 * i]     = __floats2half2_rn(v.x, v.y);
        out[2 * i + 1] = __floats2half2_rn(v.z, v.w);
    }
}

__global__ void k_transH(const float* __restrict__ in, __half* __restrict__ out,
                         int K, int N)
{
    __shared__ float t[32][33];
    const int n0 = blockIdx.x * 32, k0 = blockIdx.y * 32;
#pragma unroll
    for (int i = 0; i < 4; i++) {
        int kk = threadIdx.y + i * 8;
        t[kk][threadIdx.x] = in[(size_t)(k0 + kk) * N + n0 + threadIdx.x];
    }
    __syncthreads();
#pragma unroll
    for (int i = 0; i < 4; i++) {
        int nn = threadIdx.y + i * 8;
        out[(size_t)(n0 + nn) * K + k0 + threadIdx.x] = __float2half(t[threadIdx.x][nn]);
    }
}

__global__ void k_projH(const float* __restrict__ proj, __half* __restrict__ ph)
{
    int i = blockIdx.x * 256 + threadIdx.x;
    if (i < MMF * DHH)
        ph[i] = __float2half(proj[i] * 0.35355339059327373f);
}

__global__ void k_kvred(const float4* __restrict__ part, __half2* __restrict__ kv)
{
    int i = blockIdx.x * 256 + threadIdx.x;
    if (i < KVN / 4) {
        float4 a = part[i];
        float4 b = part[i + KVN / 4];
        float4 c = part[i + 2 * (KVN / 4)];
        float4 d = part[i + 3 * (KVN / 4)];
        kv[2 * i]     = __floats2half2_rn(a.x + b.x + c.x + d.x, a.y + b.y + c.y + d.y);
        kv[2 * i + 1] = __floats2half2_rn(a.z + b.z + c.z + d.z, a.w + b.w + c.w + d.w);
    }
}

__global__ void k_ksum(const __half* __restrict__ kp, float* __restrict__ ksum)
{
    int z = blockIdx.y;
    int b = z >> 4, h = z & 15;
    int m = threadIdx.x;
    size_t base = (size_t)b * 16777216 + (size_t)h * 256 + m;
    float s = 0.f;
    int l0 = blockIdx.x * 512;
    for (int l = l0; l < l0 + 512; l++) s += __half2float(kp[base + (size_t)l * 4096]);
    atomicAdd(&ksum[z * 256 + m], s);
}

__global__ void k_denom(const __half* __restrict__ qp, const float* __restrict__ ksum,
                        float* __restrict__ den)
{
    size_t w   = ((size_t)blockIdx.x * blockDim.x + threadIdx.x) >> 5;
    int   lane = threadIdx.x & 31;
    int   b    = (int)(w >> 16);
    int   h    = (int)(w & 15);
    const __half2* row = (const __half2*)(qp + w * 256);
    const float4*  ks  = (const float4*)(ksum + ((size_t)b * 16 + h) * 256);
    float4 k0 = ks[lane * 2], k1 = ks[lane * 2 + 1];
    float2 a0 = __half22float2(row[lane * 4]);
    float2 a1 = __half22float2(row[lane * 4 + 1]);
    float2 a2 = __half22float2(row[lane * 4 + 2]);
    float2 a3 = __half22float2(row[lane * 4 + 3]);
    float s = a0.x * k0.x + a0.y * k0.y + a1.x * k0.z + a1.y * k0.w
            + a2.x * k1.x + a2.y * k1.y + a3.x * k1.z + a3.y * k1.w;
#pragma unroll
    for (int o = 16; o; o >>= 1) s += __shfl_xor_sync(0xffffffffu, s, o);
    if (lane == 0) den[w] = s;
}

template<bool WRITE_H>
__global__ void k_ln(const float* __restrict__ a, const float* __restrict__ r,
                     const float* __restrict__ g, const float* __restrict__ b,
                     float* __restrict__ out, __half* __restrict__ outh)
{
    const int row = blockIdx.x;
    const int t   = threadIdx.x;
    const size_t base = (size_t)row * 1024;
    float4 xa = *(const float4*)(a + base + t * 4);
    float4 xr = *(const float4*)(r + base + t * 4);
    float4 s  = make_float4(xa.x + xr.x, xa.y + xr.y, xa.z + xr.z, xa.w + xr.w);
    float sum = s.x + s.y + s.z + s.w;
    float sq  = s.x * s.x + s.y * s.y + s.z * s.z + s.w * s.w;
#pragma unroll
    for (int o = 16; o; o >>= 1) {
        sum += __shfl_xor_sync(0xffffffffu, sum, o);
        sq  += __shfl_xor_sync(0xffffffffu, sq,  o);
    }
    __shared__ float ssum[8], ssq[8];
    __shared__ float s_mu, s_inv;
    int w = t >> 5;
    if ((t & 31) == 0) { ssum[w] = sum; ssq[w] = sq; }
    __syncthreads();
    if (t == 0) {
        float ts = 0.f, tq = 0.f;
        for (int i = 0; i < 8; i++) { ts += ssum[i]; tq += ssq[i]; }
        float mu  = ts * (1.f / 1024.f);
        float var = tq * (1.f / 1024.f) - mu * mu;
        s_mu = mu;
        s_inv = rsqrtf(var + 1e-6f);
    }
    __syncthreads();
    float mu = s_mu, inv = s_inv;
    float4 gg = *(const float4*)(g + t * 4);
    float4 bb = *(const float4*)(b + t * 4);
    float4 o = make_float4((s.x - mu) * inv * gg.x + bb.x,
                           (s.y - mu) * inv * gg.y + bb.y,
                           (s.z - mu) * inv * gg.z + bb.z,
                           (s.w - mu) * inv * gg.w + bb.w);
    *(float4*)(out + base + t * 4) = o;
    if (WRITE_H) {
        __half2* oh = (__half2*)(outh + base + t * 4);
        oh[0] = __floats2half2_rn(o.x, o.y);
        oh[1] = __floats2half2_rn(o.z, o.w);
    }
}

// ---------------- driver -----------------------------------------------------
extern "C" void kernel_launch(void* const* d_in, const int* in_sizes, int n_in,
                              void* d_out, int out_size)
{
    const float* x    = (const float*)d_in[0];
    const float* wq   = (const float*)d_in[1];
    const float* wk   = (const float*)d_in[2];
    const float* wv   = (const float*)d_in[3];
    const float* wo   = (const float*)d_in[4];
    const float* proj = (const float*)d_in[5];
    const float* ln1g = (const float*)d_in[6];
    const float* ln1b = (const float*)d_in[7];
    const float* ln2g = (const float*)d_in[8];
    const float* ln2b = (const float*)d_in[9];
    const float* w1   = (const float*)d_in[10];
    const float* b1   = (const float*)d_in[11];
    const float* w2   = (const float*)d_in[12];
    const float* b2   = (const float*)d_in[13];
    float* out = (float*)d_out;

    float *p_kvp, *p_ksum, *p_den, *p_tmp, *p_out1;
    __half *p_xh, *p_qh, *p_kh, *p_vh, *p_qph, *p_kph, *p_kvh;
    __half *p_out1h, *p_attnh, *p_hh, *p_projh;
    __half *p_wqkvT, *p_woT, *p_w1T, *p_w2T;
    unsigned* p_kmax;
    cudaGetSymbolAddress((void**)&p_kvp,   g_kvp);
    cudaGetSymbolAddress((void**)&p_ksum,  g_ksum);
    cudaGetSymbolAddress((void**)&p_den,   g_den);
    cudaGetSymbolAddress((void**)&p_tmp,   g_tmp);
    cudaGetSymbolAddress((void**)&p_out1,  g_out1);
    cudaGetSymbolAddress((void**)&p_kmax,  g_kmax);
    cudaGetSymbolAddress((void**)&p_xh,    g_xh);
    cudaGetSymbolAddress((void**)&p_qh,    g_qh);
    cudaGetSymbolAddress((void**)&p_kh,    g_kh);
    cudaGetSymbolAddress((void**)&p_vh,    g_vh);
    cudaGetSymbolAddress((void**)&p_qph,   g_qph);
    cudaGetSymbolAddress((void**)&p_kph,   g_kph);
    cudaGetSymbolAddress((void**)&p_kvh,   g_kvh);
    cudaGetSymbolAddress((void**)&p_out1h, g_out1h);
    cudaGetSymbolAddress((void**)&p_attnh, g_attnh);
    cudaGetSymbolAddress((void**)&p_hh,    g_hh);
    cudaGetSymbolAddress((void**)&p_projh, g_projh);
    cudaGetSymbolAddress((void**)&p_wqkvT, g_wqkvT);
    cudaGetSymbolAddress((void**)&p_woT,   g_woT);
    cudaGetSymbolAddress((void**)&p_w1T,   g_w1T);
    cudaGetSymbolAddress((void**)&p_w2T,   g_w2T);

    // prep: x->fp16, pack transposed qkv weights into one [3072][1024] buffer
    k_half4<<<(NT * DD / 4 + 255) / 256, 256>>>((const float4*)x, (__half2*)p_xh, NT * DD / 4);
    k_transH<<<dim3(32, 32), dim3(32, 8)>>>(wq, p_wqkvT,               DD, DD);
    k_transH<<<dim3(32, 32), dim3(32, 8)>>>(wk, p_wqkvT + DD * DD,     DD, DD);
    k_transH<<<dim3(32, 32), dim3(32, 8)>>>(wv, p_wqkvT + 2 * DD * DD, DD, DD);
    k_projH<<<64, 256>>>(proj, p_projh);

    // merged QKV: one GEMM, N=3072, epilogue routes slices to qh/kh/vh
    hgemm512<EPI_NONE, __half, true><<<dim3(12, 128), 512>>>(
        p_xh, p_wqkvT, nullptr, p_qh, p_kh, p_vh, NT, 3072, 1024);

    // remaining prep
    k_transH<<<dim3(32, 32),  dim3(32, 8)>>>(wo, p_woT, DD, DD);
    k_transH<<<dim3(128, 32), dim3(32, 8)>>>(w1, p_w1T, DD, DFF);
    k_transH<<<dim3(32, 128), dim3(32, 8)>>>(w2, p_w2T, DFF, DD);

    cudaMemsetAsync(p_kmax, 0, 4);
    cudaMemsetAsync(p_ksum, 0, BB * HH * MMF * sizeof(float));

    // fused dd + feature maps
    ddexp<DD_Q>   <<<NR / 64, 256>>>(p_qh, p_projh, p_qph, nullptr);
    ddexp<DD_KMAX><<<NR / 64, 256>>>(p_kh, p_projh, nullptr, p_kmax);
    ddexp<DD_KEXP><<<NR / 64, 256>>>(p_kh, p_projh, p_kph, p_kmax);

    // kv partials: fp16 split-K=4 over K=4096 (each 1024)
    hgemm_bh<true, false, float, 4><<<dim3(1, 2, 256), 256>>>(
        p_kph, (size_t)16777216, (size_t)256, 4096,
        p_vh,  (size_t)4194304,  (size_t)64,  1024,
        p_kvp, (size_t)(16 * 16384), (size_t)16384, 64, (size_t)KVN,
        nullptr, 0, 0, 0,
        256, 64, 1024);
    k_kvred<<<(KVN / 4 + 255) / 256, 256>>>((const float4*)p_kvp, (__half2*)p_kvh);

    k_ksum<<<dim3(8, 64), 256>>>(p_kph, p_ksum);
    k_denom<<<NR / 8, 256>>>(p_qph, p_ksum, p_den);

    // attn = (qp @ kv) / denom : fp16 -> fp16
    hgemm_bh<false, true, __half, 1><<<dim3(1, 32, 64), 256>>>(
        p_qph, (size_t)16777216, (size_t)256, 4096,
        p_kvh, (size_t)(16 * 16384), (size_t)16384, 64,
        p_attnh, (size_t)4194304, (size_t)64, 1024, (size_t)0,
        p_den,  (size_t)65536,   (size_t)1,  16,
        4096, 64, 256);

    // attn_out = attn @ wo^T -> fp32 tmp
    hgemm512<EPI_NONE, float, false><<<dim3(4, 128), 512>>>(
        p_attnh, p_woT, nullptr, p_tmp, nullptr, nullptr, NT, 1024, 1024);

    // out1 = LN(x + attn_out) -> fp32 + fp16
    k_ln<true><<<NT, 256>>>(p_tmp, x, ln1g, ln1b, p_out1, p_out1h);

    // FFN
    hgemm512<EPI_BIAS_ELU, __half, false><<<dim3(16, 128), 512>>>(
        p_out1h, p_w1T, b1, p_hh, nullptr, nullptr, NT, DFF, 1024);
    hgemm512<EPI_BIAS, float, false><<<dim3(4, 128), 512>>>(
        p_hh, p_w2T, b2, p_tmp, nullptr, nullptr, NT, 1024, DFF);

    // out2 = LN(out1 + ffn)
    k_ln<false><<<NT, 256>>>(p_tmp, p_out1, ln2g, ln2b, out, nullptr);
}

// round 14
// speedup vs baseline: 1.1277x; 1.1277x over previous
#include <cuda_runtime.h>
#include <cuda_fp16.h>
#include <math.h>
#include <stdint.h>

#define BB   4
#define LL   4096
#define DD   1024
#define HH   16
#define DHH  64
#define MMF  256
#define DFF  4096
#define NT   (BB*LL)      /* 16384 tokens  */
#define NR   (NT*HH)      /* 262144 (t,h) rows */
#define KVN  (BB*HH*MMF*DHH)   /* 1048576 */

// ---------------- scratch (device globals; no allocation allowed) ----------
__device__ float  g_kvp  [4*KVN];
__device__ float  g_ksum [BB*HH*MMF];
__device__ float  g_den  [NR];
__device__ float  g_tmp  [(size_t)NT*DD];
__device__ float  g_out1 [(size_t)NT*DD];
__device__ unsigned g_kmax;
// fp16 buffers
__device__ __half g_xh   [(size_t)NT*DD];
__device__ __half g_qh   [(size_t)NT*DD];
__device__ __half g_kh   [(size_t)NT*DD];
__device__ __half g_vh   [(size_t)NT*DD];
__device__ __half g_qph  [(size_t)NR*MMF];
__device__ __half g_kph  [(size_t)NR*MMF];
__device__ __half g_kvh  [KVN];
__device__ __half g_out1h[(size_t)NT*DD];
__device__ __half g_attnh[(size_t)NT*DD];
__device__ __half g_hh   [(size_t)NT*DFF];
__device__ __half g_projh[MMF*DHH];
__device__ __half g_wqkvT[3*DD*DD];             // packed [3072][1024]
__device__ __half g_woT  [DD*DD];
__device__ __half g_w1T  [(size_t)DFF*DD];
__device__ __half g_w2T  [(size_t)DD*DFF];

enum { EPI_NONE = 0, EPI_BIAS = 1, EPI_BIAS_ELU = 2 };
enum { DD_Q = 0, DD_KMAX = 1, DD_KEXP = 2 };

// ---------------- helpers ----------------------------------------------------
__device__ __forceinline__ void mma_f16(float* d, const unsigned* a,
                                        const unsigned* b)
{
    asm volatile(
        "mma.sync.aligned.m16n8k16.row.col.f32.f16.f16.f32 "
        "{%0,%1,%2,%3}, {%4,%5,%6,%7}, {%8,%9}, {%0,%1,%2,%3};\n"
        : "+f"(d[0]), "+f"(d[1]), "+f"(d[2]), "+f"(d[3])
        : "r"(a[0]), "r"(a[1]), "r"(a[2]), "r"(a[3]),
          "r"(b[0]), "r"(b[1]));
}

__device__ __forceinline__ void ldsm_x4(unsigned* r, unsigned addr)
{
    asm volatile("ldmatrix.sync.aligned.m8n8.x4.shared.b16 {%0,%1,%2,%3}, [%4];"
        : "=r"(r[0]), "=r"(r[1]), "=r"(r[2]), "=r"(r[3]) : "r"(addr));
}

__device__ __forceinline__ void ldsm_x4t(unsigned* r, unsigned addr)
{
    asm volatile("ldmatrix.sync.aligned.m8n8.x4.trans.shared.b16 {%0,%1,%2,%3}, [%4];"
        : "=r"(r[0]), "=r"(r[1]), "=r"(r[2]), "=r"(r[3]) : "r"(addr));
}

__device__ __forceinline__ float unflip(unsigned u)
{
    return __uint_as_float((u & 0x80000000u) ? (u ^ 0x80000000u) : ~u);
}

__device__ __forceinline__ __half2 h2ex2(__half2 x)
{
    unsigned u = *(unsigned*)&x, y;
    asm("ex2.approx.f16x2 %0, %1;" : "=r"(y) : "r"(u));
    return *(__half2*)&y;
}

// ---------------- fp16 tensor-core GEMM: C[M,N] = A[M,K] @ B^T ----------------
// R12-proven: 128x128 CTA tile, 256 threads = 8 warps (4m x 2n), warp tile
// 32x64, ldmatrix, double-buffered, one sync/iter, 2 CTAs/SM.
// SPLIT3: N covers 3 packed 1024-col outputs; each 128-col CTA tile lies in
// exactly one slice -> route to C/C2/C3 (fp16), stride 1024.
#define HS 40
#define HBUF (128 * HS)
#define HBUFB (HBUF * 2)

template<int EPI, typename OutT, bool SPLIT3>
__global__ __launch_bounds__(256, 2)
void hgemm(const __half* __restrict__ A, const __half* __restrict__ B,
           const float* __restrict__ bias, OutT* __restrict__ C,
           __half* __restrict__ C2, __half* __restrict__ C3,
           int M, int N, int K)
{
    __shared__ __align__(16) __half As[2 * HBUF];
    __shared__ __align__(16) __half Bs[2 * HBUF];

    const int tid  = threadIdx.x;
    const int wid  = tid >> 5;
    const int lane = tid & 31;
    const int wm   = (wid >> 1) * 32;
    const int wn   = (wid & 1)  * 64;
    const size_t m0 = (size_t)blockIdx.y * 128;
    const int    n0 = blockIdx.x * 128;

    const int ar0 = tid >> 2,          aq0 = (tid & 3) << 3;
    const int ar1 = (tid + 256) >> 2,  aq1 = ((tid + 256) & 3) << 3;

    const int matid = lane >> 3, rowin = lane & 7;
    const unsigned sAb = (unsigned)__cvta_generic_to_shared(As);
    const unsigned sBb = (unsigned)__cvta_generic_to_shared(Bs);
    unsigned aoff[2], boff[4];
#pragma unroll
    for (int mt = 0; mt < 2; mt++)
        aoff[mt] = sAb + (unsigned)(((wm + mt * 16 + rowin + ((matid & 1) << 3)) * HS
                                     + ((matid & 2) << 2)) << 1);
#pragma unroll
    for (int p = 0; p < 4; p++)
        boff[p] = sBb + (unsigned)(((wn + ((p << 1) + ((matid >> 1) & 1)) * 8 + rowin) * HS
                                     + ((matid & 1) << 3)) << 1);

    uint4 ra0, ra1, rb0, rb1;
    float acc[2][8][4];
#pragma unroll
    for (int mt = 0; mt < 2; mt++)
#pragma unroll
        for (int nt = 0; nt < 8; nt++)
#pragma unroll
            for (int i = 0; i < 4; i++) acc[mt][nt][i] = 0.f;

    const int iters = K >> 5;

    ra0 = *(const uint4*)(A + (m0 + ar0) * K + aq0);
    ra1 = *(const uint4*)(A + (m0 + ar1) * K + aq1);
    rb0 = *(const uint4*)(B + (size_t)(n0 + ar0) * K + aq0);
    rb1 = *(const uint4*)(B + (size_t)(n0 + ar1) * K + aq1);
    *(uint4*)&As[ar0 * HS + aq0] = ra0;
    *(uint4*)&As[ar1 * HS + aq1] = ra1;
    *(uint4*)&Bs[ar0 * HS + aq0] = rb0;
    *(uint4*)&Bs[ar1 * HS + aq1] = rb1;
    __syncthreads();

    for (int it = 0; it < iters; it++) {
        const bool more = (it + 1 < iters);
        if (more) {
            int k0 = (it + 1) << 5;
            ra0 = *(const uint4*)(A + (m0 + ar0) * K + k0 + aq0);
            ra1 = *(const uint4*)(A + (m0 + ar1) * K + k0 + aq1);
            rb0 = *(const uint4*)(B + (size_t)(n0 + ar0) * K + k0 + aq0);
            rb1 = *(const uint4*)(B + (size_t)(n0 + ar1) * K + k0 + aq1);
        }

        const unsigned bo = (unsigned)((it & 1) * HBUFB);
#pragma unroll
        for (int ks = 0; ks < 2; ks++) {
            const unsigned cb = bo + (unsigned)(ks << 5);
            unsigned af[2][4], bf[4][4];
#pragma unroll
            for (int mt = 0; mt < 2; mt++) ldsm_x4(af[mt], aoff[mt] + cb);
#pragma unroll
            for (int p = 0; p < 4; p++)   ldsm_x4(bf[p],  boff[p]  + cb);
#pragma unroll
            for (int mt = 0; mt < 2; mt++)
#pragma unroll
                for (int p = 0; p < 4; p++) {
                    mma_f16(acc[mt][2 * p],     af[mt], &bf[p][0]);
                    mma_f16(acc[mt][2 * p + 1], af[mt], &bf[p][2]);
                }
        }

        if (more) {
            const int s = ((it + 1) & 1) * HBUF;
            *(uint4*)&As[s + ar0 * HS + aq0] = ra0;
            *(uint4*)&As[s + ar1 * HS + aq1] = ra1;
            *(uint4*)&Bs[s + ar0 * HS + aq0] = rb0;
            *(uint4*)&Bs[s + ar1 * HS + aq1] = rb1;
        }
        __syncthreads();
    }

    // SPLIT3 routing (CTA-constant)
    __half* Ch = nullptr;
    if (SPLIT3) {
        const int slice = n0 >> 10;
        Ch = (slice == 0) ? (__half*)C : ((slice == 1) ? C2 : C3);
    }

#pragma unroll
    for (int mt = 0; mt < 2; mt++) {
#pragma unroll
        for (int nt = 0; nt < 8; nt++) {
            size_t row = m0 + wm + mt * 16 + (lane >> 2);
            int gcol = n0 + wn + nt * 8 + ((lane & 3) << 1);
            float2 lo = make_float2(acc[mt][nt][0], acc[mt][nt][1]);
            float2 hi = make_float2(acc[mt][nt][2], acc[mt][nt][3]);
            if (EPI == EPI_BIAS || EPI == EPI_BIAS_ELU) {
                float2 bb = *(const float2*)(bias + gcol);
                lo.x += bb.x; lo.y += bb.y;
                hi.x += bb.x; hi.y += bb.y;
            }
            if (EPI == EPI_BIAS_ELU) {
                lo.x = lo.x > 0.f ? lo.x : expm1f(lo.x);
                lo.y = lo.y > 0.f ? lo.y : expm1f(lo.y);
                hi.x = hi.x > 0.f ? hi.x : expm1f(hi.x);
                hi.y = hi.y > 0.f ? hi.y : expm1f(hi.y);
            }
            if (SPLIT3) {
                int col = gcol & 1023;
                *(__half2*)(Ch + row * 1024 + col)       = __floats2half2_rn(lo.x, lo.y);
                *(__half2*)(Ch + (row + 8) * 1024 + col) = __floats2half2_rn(hi.x, hi.y);
            } else if (sizeof(OutT) == 2) {
                *(__half2*)((__half*)C + row * N + gcol)       = __floats2half2_rn(lo.x, lo.y);
                *(__half2*)((__half*)C + (row + 8) * N + gcol) = __floats2half2_rn(hi.x, hi.y);
            } else {
                *(float2*)((float*)C + row * N + gcol)       = lo;
                *(float2*)((float*)C + (row + 8) * N + gcol) = hi;
            }
        }
    }
}

// ---------------- fused dd GEMM + Performer feature map -----------------------
// (unchanged from R12 — proven)
#define DS 72

template<int MODE>
__global__ __launch_bounds__(256, 2)
void ddexp(const __half* __restrict__ A, const __half* __restrict__ Bp,
           __half* __restrict__ outp, unsigned* __restrict__ gmax)
{
    __shared__ __align__(16) __half As[64 * DS];
    __shared__ __align__(16) __half Bs[256 * DS];
    __shared__ float sdiag[64];
    __shared__ float srmax[4][64];

    const int tid  = threadIdx.x;
    const int wid  = tid >> 5;
    const int lane = tid & 31;
    const int wm   = (wid >> 2) * 32;
    const int wn   = (wid & 3)  * 64;
    const size_t m0 = (size_t)blockIdx.x * 64;

#pragma unroll
    for (int i = 0; i < 2; i++) {
        int c = tid + i * 256;
        int r = c >> 3, cc = (c & 7) << 3;
        *(uint4*)&As[r * DS + cc] = *(const uint4*)(A + (m0 + r) * 64 + cc);
    }
#pragma unroll
    for (int i = 0; i < 8; i++) {
        int c = tid + i * 256;
        int r = c >> 3, cc = (c & 7) << 3;
        *(uint4*)&Bs[r * DS + cc] = *(const uint4*)(Bp + (size_t)r * 64 + cc);
    }
    __syncthreads();

    if (MODE != DD_KMAX && tid < 64) {
        const __half2* row = (const __half2*)&As[tid * DS];
        float ss = 0.f;
#pragma unroll
        for (int i = 0; i < 32; i++) {
            float2 v = __half22float2(row[i]);
            ss += v.x * v.x + v.y * v.y;
        }
        sdiag[tid] = ss;
    }

    const int matid = lane >> 3, rowin = lane & 7;
    const unsigned sA = (unsigned)__cvta_generic_to_shared(As);
    const unsigned sB = (unsigned)__cvta_generic_to_shared(Bs);
    unsigned aoff[2], boff[4];
#pragma unroll
    for (int mt = 0; mt < 2; mt++)
        aoff[mt] = sA + (unsigned)(((wm + mt * 16 + rowin + ((matid & 1) << 3)) * DS
                                    + ((matid & 2) << 2)) << 1);
#pragma unroll
    for (int p = 0; p < 4; p++)
        boff[p] = sB + (unsigned)(((wn + ((p << 1) + ((matid >> 1) & 1)) * 8 + rowin) * DS
                                    + ((matid & 1) << 3)) << 1);

    float acc[2][8][4];
#pragma unroll
    for (int mt = 0; mt < 2; mt++)
#pragma unroll
        for (int nt = 0; nt < 8; nt++)
#pragma unroll
            for (int i = 0; i < 4; i++) acc[mt][nt][i] = 0.f;

#pragma unroll
    for (int ks = 0; ks < 4; ks++) {
        const unsigned cb = (unsigned)(ks << 5);
        unsigned af[2][4], bf[4][4];
#pragma unroll
        for (int mt = 0; mt < 2; mt++) ldsm_x4(af[mt], aoff[mt] + cb);
#pragma unroll
        for (int p = 0; p < 4; p++)   ldsm_x4(bf[p],  boff[p]  + cb);
#pragma unroll
        for (int mt = 0; mt < 2; mt++)
#pragma unroll
            for (int p = 0; p < 4; p++) {
                mma_f16(acc[mt][2 * p],     af[mt], &bf[p][0]);
                mma_f16(acc[mt][2 * p + 1], af[mt], &bf[p][2]);
            }
    }

    if (MODE == DD_KMAX) {
        float mx = -3.4e38f;
#pragma unroll
        for (int mt = 0; mt < 2; mt++)
#pragma unroll
            for (int nt = 0; nt < 8; nt++)
#pragma unroll
                for (int i = 0; i < 4; i++) mx = fmaxf(mx, acc[mt][nt][i]);
#pragma unroll
        for (int o = 16; o; o >>= 1) mx = fmaxf(mx, __shfl_xor_sync(0xffffffffu, mx, o));
        if (lane == 0) {
            unsigned u = __float_as_uint(mx);
            u = (u & 0x80000000u) ? ~u : (u | 0x80000000u);
            atomicMax(gmax, u);
        }
        return;
    }

    if (MODE == DD_Q) {
#pragma unroll
        for (int mt = 0; mt < 2; mt++) {
            float m0v = -3.4e38f, m1v = -3.4e38f;
#pragma unroll
            for (int nt = 0; nt < 8; nt++) {
                m0v = fmaxf(m0v, fmaxf(acc[mt][nt][0], acc[mt][nt][1]));
                m1v = fmaxf(m1v, fmaxf(acc[mt][nt][2], acc[mt][nt][3]));
            }
#pragma unroll
            for (int o = 1; o <= 2; o <<= 1) {
                m0v = fmaxf(m0v, __shfl_xor_sync(0xffffffffu, m0v, o));
                m1v = fmaxf(m1v, __shfl_xor_sync(0xffffffffu, m1v, o));
            }
            if ((lane & 3) == 0) {
                srmax[wid & 3][wm + mt * 16 + (lane >> 2)]     = m0v;
                srmax[wid & 3][wm + mt * 16 + 8 + (lane >> 2)] = m1v;
            }
        }
    }
    __syncthreads();

    const float gm = (MODE == DD_KEXP) ? unflip(*gmax) : 0.f;
    const float L2E = 1.4426950408889634f;
    const __half2 eps2 = __float2half2_rn(1e-6f);
    const __half2 rat2 = __float2half2_rn(0.0625f);

#pragma unroll
    for (int mt = 0; mt < 2; mt++) {
        const int r0 = wm + mt * 16 + (lane >> 2);
        const int r1 = r0 + 8;
        float c0, c1;
        if (MODE == DD_Q) {
            float rm0 = fmaxf(fmaxf(srmax[0][r0], srmax[1][r0]),
                              fmaxf(srmax[2][r0], srmax[3][r0]));
            float rm1 = fmaxf(fmaxf(srmax[0][r1], srmax[1][r1]),
                              fmaxf(srmax[2][r1], srmax[3][r1]));
            c0 = 0.0625f * sdiag[r0] + rm0;
            c1 = 0.0625f * sdiag[r1] + rm1;
        } else {
            c0 = 0.0625f * sdiag[r0] + gm;
            c1 = 0.0625f * sdiag[r1] + gm;
        }
        const float c0l = c0 * L2E, c1l = c1 * L2E;
#pragma unroll
        for (int nt = 0; nt < 8; nt++) {
            const int col = wn + nt * 8 + ((lane & 3) << 1);
            __half2 t01 = __floats2half2_rn(fmaf(acc[mt][nt][0], L2E, -c0l),
                                            fmaf(acc[mt][nt][1], L2E, -c0l));
            __half2 t23 = __floats2half2_rn(fmaf(acc[mt][nt][2], L2E, -c1l),
                                            fmaf(acc[mt][nt][3], L2E, -c1l));
            __half2 e01 = __hmul2(__hadd2(h2ex2(t01), eps2), rat2);
            __half2 e23 = __hmul2(__hadd2(h2ex2(t23), eps2), rat2);
            *(__half2*)(outp + (m0 + r0) * 256 + col) = e01;
            *(__half2*)(outp + (m0 + r1) * 256 + col) = e23;
        }
    }
}

// ------------- fp16 batched strided GEMM over (b,h), optional split-K --------
// (unchanged — proven)
#define BAS 136
#define NAS 40
#define BBS 72

template<bool TRANSA, bool DIV, typename OutT, int NSPLIT>
__global__ __launch_bounds__(256, 2)
void hgemm_bh(const __half* __restrict__ A, size_t sAb, size_t sAh, int lda,
              const __half* __restrict__ B, size_t sBb, size_t sBh, int ldb,
              OutT* __restrict__ C, size_t sCb, size_t sCh, int ldc, size_t sCsplit,
              const float* __restrict__ aux, size_t sXb, size_t sXh, int ldx,
              int M, int N, int K)
{
    constexpr int ABUFH = TRANSA ? (32 * BAS) : (128 * NAS);
    constexpr int BBUFH = 32 * BBS;
    __shared__ __align__(16) __half As[2 * ABUFH];
    __shared__ __align__(16) __half Bs[2 * BBUFH];

    const int z     = blockIdx.z;
    const int split = (NSPLIT > 1) ? (z >> 6) : 0;
    const int zz    = (NSPLIT > 1) ? (z & 63) : z;
    const int zb = zz >> 4, zh = zz & 15;
    const __half* Ab = A + (size_t)zb * sAb + (size_t)zh * sAh;
    const __half* Bb = B + (size_t)zb * sBb + (size_t)zh * sBh;
    OutT*         Cb = C + (size_t)zb * sCb + (size_t)zh * sCh
                         + (size_t)split * sCsplit;
    if (NSPLIT > 1) {
        Ab += (size_t)split * K * lda;
        Bb += (size_t)split * K * ldb;
    }

    const int tid  = threadIdx.x;
    const int wid  = tid >> 5;
    const int lane = tid & 31;
    const int wm   = (wid >> 1) * 32;
    const int wn   = (wid & 1)  * 32;
    const int m0   = blockIdx.y * 128;

    const int matid = lane >> 3, rowin = lane & 7;
    const unsigned sAs = (unsigned)__cvta_generic_to_shared(As);
    const unsigned sBs = (unsigned)__cvta_generic_to_shared(Bs);

    unsigned aoff[2], boff[2];
#pragma unroll
    for (int mt = 0; mt < 2; mt++) {
        if (TRANSA)
            aoff[mt] = sAs + (unsigned)(((rowin + ((matid >> 1) << 3)) * BAS
                                         + wm + mt * 16 + ((matid & 1) << 3)) << 1);
        else
            aoff[mt] = sAs + (unsigned)(((wm + mt * 16 + rowin + ((matid & 1) << 3)) * NAS
                                         + ((matid & 2) << 2)) << 1);
    }
#pragma unroll
    for (int p = 0; p < 2; p++)
        boff[p] = sBs + (unsigned)(((rowin + ((matid & 1) << 3)) * BBS
                                    + wn + (p << 4) + ((matid >> 1) << 3)) << 1);

    const int ta_kr = tid >> 4, ta_mc = (tid & 15) << 3;
    const int na_r0 = tid >> 2, na_k0 = (tid & 3) << 3;
    const int b_kr  = tid >> 3, b_nc  = (tid & 7) << 3;

    uint4 ra0, ra1, rb;
    float acc[2][4][4];
#pragma unroll
    for (int mt = 0; mt < 2; mt++)
#pragma unroll
        for (int nt = 0; nt < 4; nt++)
#pragma unroll
            for (int i = 0; i < 4; i++) acc[mt][nt][i] = 0.f;

    const int iters = K >> 5;

    auto ld = [&](int k0) {
        if (TRANSA) {
            ra0 = *(const uint4*)(Ab + (size_t)(k0 + ta_kr)      * lda + m0 + ta_mc);
            ra1 = *(const uint4*)(Ab + (size_t)(k0 + ta_kr + 16) * lda + m0 + ta_mc);
        } else {
            ra0 = *(const uint4*)(Ab + (size_t)(m0 + na_r0)      * lda + k0 + na_k0);
            ra1 = *(const uint4*)(Ab + (size_t)(m0 + na_r0 + 64) * lda + k0 + na_k0);
        }
        rb = *(const uint4*)(Bb + (size_t)(k0 + b_kr) * ldb + b_nc);
    };
    auto st = [&](int s) {
        __half* as = As + s * ABUFH;
        __half* bs = Bs + s * BBUFH;
        if (TRANSA) {
            *(uint4*)&as[ta_kr * BAS + ta_mc]        = ra0;
            *(uint4*)&as[(ta_kr + 16) * BAS + ta_mc] = ra1;
        } else {
            *(uint4*)&as[na_r0 * NAS + na_k0]        = ra0;
            *(uint4*)&as[(na_r0 + 64) * NAS + na_k0] = ra1;
        }
        *(uint4*)&bs[b_kr * BBS + b_nc] = rb;
    };

    ld(0); st(0);
    __syncthreads();

    for (int it = 0; it < iters; it++) {
        const bool more = (it + 1 < iters);
        if (more) ld((it + 1) << 5);

        const unsigned ab = (unsigned)((it & 1) * (ABUFH * 2));
        const unsigned bb = (unsigned)((it & 1) * (BBUFH * 2));
#pragma unroll
        for (int ks = 0; ks < 2; ks++) {
            const unsigned aks = TRANSA ? (unsigned)(ks * 16 * BAS * 2) : (unsigned)(ks << 5);
            const unsigned bks = (unsigned)(ks * 16 * BBS * 2);
            unsigned af[2][4], bf[2][4];
#pragma unroll
            for (int mt = 0; mt < 2; mt++) {
                if (TRANSA) ldsm_x4t(af[mt], aoff[mt] + ab + aks);
                else        ldsm_x4 (af[mt], aoff[mt] + ab + aks);
            }
#pragma unroll
            for (int p = 0; p < 2; p++) ldsm_x4t(bf[p], boff[p] + bb + bks);
#pragma unroll
            for (int mt = 0; mt < 2; mt++)
#pragma unroll
                for (int p = 0; p < 2; p++) {
                    mma_f16(acc[mt][2 * p],     af[mt], &bf[p][0]);
                    mma_f16(acc[mt][2 * p + 1], af[mt], &bf[p][2]);
                }
        }

        if (more) st((it + 1) & 1);
        __syncthreads();
    }

#pragma unroll
    for (int mt = 0; mt < 2; mt++) {
        int row = m0 + wm + mt * 16 + (lane >> 2);
        float dv0 = 1.f, dv1 = 1.f;
        if (DIV) {
            dv0 = 1.f / aux[(size_t)zb * sXb + (size_t)zh * sXh + (size_t)row * ldx];
            dv1 = 1.f / aux[(size_t)zb * sXb + (size_t)zh * sXh + (size_t)(row + 8) * ldx];
        }
#pragma unroll
        for (int nt = 0; nt < 4; nt++) {
            int col = wn + nt * 8 + ((lane & 3) << 1);
            float2 lo = make_float2(acc[mt][nt][0] * dv0, acc[mt][nt][1] * dv0);
            float2 hi = make_float2(acc[mt][nt][2] * dv1, acc[mt][nt][3] * dv1);
            if (sizeof(OutT) == 2) {
                *(__half2*)((__half*)Cb + (size_t)row * ldc + col)       = __floats2half2_rn(lo.x, lo.y);
                *(__half2*)((__half*)Cb + (size_t)(row + 8) * ldc + col) = __floats2half2_rn(hi.x, hi.y);
            } else {
                *(float2*)((float*)Cb + (size_t)row * ldc + col)       = lo;
                *(float2*)((float*)Cb + (size_t)(row + 8) * ldc + col) = hi;
            }
        }
    }
}

// ---------------- small helper kernels --------------------------------------
__global__ void k_half4(const float4* __restrict__ in, __half2* __restrict__ out,
                        int n4)
{
    int i = blockIdx.x * 256 + threadIdx.x;
    if (i < n4) {
        float4 v = in[i];
        out[2 * i]     = __floats2half2_rn(v.x, v.y);
        out[2 * i + 1] = __floats2half2_rn(v.z, v.w);
    }
}

__global__ void k_transH(const float* __restrict__ in, __half* __restrict__ out,
                         int K, int N)
{
    __shared__ float t[32][33];
    const int n0 = blockIdx.x * 32, k0 = blockIdx.y * 32;
#pragma unroll
    for (int i = 0; i < 4; i++) {
        int kk = threadIdx.y + i * 8;
        t[kk][threadIdx.x] = in[(size_t)(k0 + kk) * N + n0 + threadIdx.x];
    }
    __syncthreads();
#pragma unroll
    for (int i = 0; i < 4; i++) {
        int nn = threadIdx.y + i * 8;
        out[(size_t)(n0 + nn) * K + k0 + threadIdx.x] = __float2half(t[threadIdx.x][nn]);
    }
}

__global__ void k_projH(const float* __restrict__ proj, __half* __restrict__ ph)
{
    int i = blockIdx.x * 256 + threadIdx.x;
    if (i < MMF * DHH)
        ph[i] = __float2half(proj[i] * 0.35355339059327373f);
}

__global__ void k_kvred(const float4* __restrict__ part, __half2* __restrict__ kv)
{
    int i = blockIdx.x * 256 + threadIdx.x;
    if (i < KVN / 4) {
        float4 a = part[i];
        float4 b = part[i + KVN / 4];
        float4 c = part[i + 2 * (KVN / 4)];
        float4 d = part[i + 3 * (KVN / 4)];
        kv[2 * i]     = __floats2half2_rn(a.x + b.x + c.x + d.x, a.y + b.y + c.y + d.y);
        kv[2 * i + 1] = __floats2half2_rn(a.z + b.z + c.z + d.z, a.w + b.w + c.w + d.w);
    }
}

__global__ void k_ksum(const __half* __restrict__ kp, float* __restrict__ ksum)
{
    int z = blockIdx.y;
    int b = z >> 4, h = z & 15;
    int m = threadIdx.x;
    size_t base = (size_t)b * 16777216 + (size_t)h * 256 + m;
    float s = 0.f;
    int l0 = blockIdx.x * 512;
    for (int l = l0; l < l0 + 512; l++) s += __half2float(kp[base + (size_t)l * 4096]);
    atomicAdd(&ksum[z * 256 + m], s);
}

__global__ void k_denom(const __half* __restrict__ qp, const float* __restrict__ ksum,
                        float* __restrict__ den)
{
    size_t w   = ((size_t)blockIdx.x * blockDim.x + threadIdx.x) >> 5;
    int   lane = threadIdx.x & 31;
    int   b    = (int)(w >> 16);
    int   h    = (int)(w & 15);
    const __half2* row = (const __half2*)(qp + w * 256);
    const float4*  ks  = (const float4*)(ksum + ((size_t)b * 16 + h) * 256);
    float4 k0 = ks[lane * 2], k1 = ks[lane * 2 + 1];
    float2 a0 = __half22float2(row[lane * 4]);
    float2 a1 = __half22float2(row[lane * 4 + 1]);
    float2 a2 = __half22float2(row[lane * 4 + 2]);
    float2 a3 = __half22float2(row[lane * 4 + 3]);
    float s = a0.x * k0.x + a0.y * k0.y + a1.x * k0.z + a1.y * k0.w
            + a2.x * k1.x + a2.y * k1.y + a3.x * k1.z + a3.y * k1.w;
#pragma unroll
    for (int o = 16; o; o >>= 1) s += __shfl_xor_sync(0xffffffffu, s, o);
    if (lane == 0) den[w] = s;
}

template<bool WRITE_H>
__global__ void k_ln(const float* __restrict__ a, const float* __restrict__ r,
                     const float* __restrict__ g, const float* __restrict__ b,
                     float* __restrict__ out, __half* __restrict__ outh)
{
    const int row = blockIdx.x;
    const int t   = threadIdx.x;
    const size_t base = (size_t)row * 1024;
    float4 xa = *(const float4*)(a + base + t * 4);
    float4 xr = *(const float4*)(r + base + t * 4);
    float4 s  = make_float4(xa.x + xr.x, xa.y + xr.y, xa.z + xr.z, xa.w + xr.w);
    float sum = s.x + s.y + s.z + s.w;
    float sq  = s.x * s.x + s.y * s.y + s.z * s.z + s.w * s.w;
#pragma unroll
    for (int o = 16; o; o >>= 1) {
        sum += __shfl_xor_sync(0xffffffffu, sum, o);
        sq  += __shfl_xor_sync(0xffffffffu, sq,  o);
    }
    __shared__ float ssum[8], ssq[8];
    __shared__ float s_mu, s_inv;
    int w = t >> 5;
    if ((t & 31) == 0) { ssum[w] = sum; ssq[w] = sq; }
    __syncthreads();
    if (t == 0) {
        float ts = 0.f, tq = 0.f;
        for (int i = 0; i < 8; i++) { ts += ssum[i]; tq += ssq[i]; }
        float mu  = ts * (1.f / 1024.f);
        float var = tq * (1.f / 1024.f) - mu * mu;
        s_mu = mu;
        s_inv = rsqrtf(var + 1e-6f);
    }
    __syncthreads();
    float mu = s_mu, inv = s_inv;
    float4 gg = *(const float4*)(g + t * 4);
    float4 bb = *(const float4*)(b + t * 4);
    float4 o = make_float4((s.x - mu) * inv * gg.x + bb.x,
                           (s.y - mu) * inv * gg.y + bb.y,
                           (s.z - mu) * inv * gg.z + bb.z,
                           (s.w - mu) * inv * gg.w + bb.w);
    *(float4*)(out + base + t * 4) = o;
    if (WRITE_H) {
        __half2* oh = (__half2*)(outh + base + t * 4);
        oh[0] = __floats2half2_rn(o.x, o.y);
        oh[1] = __floats2half2_rn(o.z, o.w);
    }
}

// ---------------- driver -----------------------------------------------------
extern "C" void kernel_launch(void* const* d_in, const int* in_sizes, int n_in,
                              void* d_out, int out_size)
{
    const float* x    = (const float*)d_in[0];
    const float* wq   = (const float*)d_in[1];
    const float* wk   = (const float*)d_in[2];
    const float* wv   = (const float*)d_in[3];
    const float* wo   = (const float*)d_in[4];
    const float* proj = (const float*)d_in[5];
    const float* ln1g = (const float*)d_in[6];
    const float* ln1b = (const float*)d_in[7];
    const float* ln2g = (const float*)d_in[8];
    const float* ln2b = (const float*)d_in[9];
    const float* w1   = (const float*)d_in[10];
    const float* b1   = (const float*)d_in[11];
    const float* w2   = (const float*)d_in[12];
    const float* b2   = (const float*)d_in[13];
    float* out = (float*)d_out;

    float *p_kvp, *p_ksum, *p_den, *p_tmp, *p_out1;
    __half *p_xh, *p_qh, *p_kh, *p_vh, *p_qph, *p_kph, *p_kvh;
    __half *p_out1h, *p_attnh, *p_hh, *p_projh;
    __half *p_wqkvT, *p_woT, *p_w1T, *p_w2T;
    unsigned* p_kmax;
    cudaGetSymbolAddress((void**)&p_kvp,   g_kvp);
    cudaGetSymbolAddress((void**)&p_ksum,  g_ksum);
    cudaGetSymbolAddress((void**)&p_den,   g_den);
    cudaGetSymbolAddress((void**)&p_tmp,   g_tmp);
    cudaGetSymbolAddress((void**)&p_out1,  g_out1);
    cudaGetSymbolAddress((void**)&p_kmax,  g_kmax);
    cudaGetSymbolAddress((void**)&p_xh,    g_xh);
    cudaGetSymbolAddress((void**)&p_qh,    g_qh);
    cudaGetSymbolAddress((void**)&p_kh,    g_kh);
    cudaGetSymbolAddress((void**)&p_vh,    g_vh);
    cudaGetSymbolAddress((void**)&p_qph,   g_qph);
    cudaGetSymbolAddress((void**)&p_kph,   g_kph);
    cudaGetSymbolAddress((void**)&p_kvh,   g_kvh);
    cudaGetSymbolAddress((void**)&p_out1h, g_out1h);
    cudaGetSymbolAddress((void**)&p_attnh, g_attnh);
    cudaGetSymbolAddress((void**)&p_hh,    g_hh);
    cudaGetSymbolAddress((void**)&p_projh, g_projh);
    cudaGetSymbolAddress((void**)&p_wqkvT, g_wqkvT);
    cudaGetSymbolAddress((void**)&p_woT,   g_woT);
    cudaGetSymbolAddress((void**)&p_w1T,   g_w1T);
    cudaGetSymbolAddress((void**)&p_w2T,   g_w2T);

    // prep: x->fp16, pack transposed qkv weights into one [3072][1024] buffer
    k_half4<<<(NT * DD / 4 + 255) / 256, 256>>>((const float4*)x, (__half2*)p_xh, NT * DD / 4);
    k_transH<<<dim3(32, 32), dim3(32, 8)>>>(wq, p_wqkvT,               DD, DD);
    k_transH<<<dim3(32, 32), dim3(32, 8)>>>(wk, p_wqkvT + DD * DD,     DD, DD);
    k_transH<<<dim3(32, 32), dim3(32, 8)>>>(wv, p_wqkvT + 2 * DD * DD, DD, DD);
    k_projH<<<64, 256>>>(proj, p_projh);

    // merged QKV: one launch, proven 128x128 tiling, slice-routed epilogue
    hgemm<EPI_NONE, __half, true><<<dim3(24, 128), 256>>>(
        p_xh, p_wqkvT, nullptr, p_qh, p_kh, p_vh, NT, 3072, 1024);

    // remaining prep
    k_transH<<<dim3(32, 32),  dim3(32, 8)>>>(wo, p_woT, DD, DD);
    k_transH<<<dim3(128, 32), dim3(32, 8)>>>(w1, p_w1T, DD, DFF);
    k_transH<<<dim3(32, 128), dim3(32, 8)>>>(w2, p_w2T, DFF, DD);

    cudaMemsetAsync(p_kmax, 0, 4);
    cudaMemsetAsync(p_ksum, 0, BB * HH * MMF * sizeof(float));

    // fused dd + feature maps
    ddexp<DD_Q>   <<<NR / 64, 256>>>(p_qh, p_projh, p_qph, nullptr);
    ddexp<DD_KMAX><<<NR / 64, 256>>>(p_kh, p_projh, nullptr, p_kmax);
    ddexp<DD_KEXP><<<NR / 64, 256>>>(p_kh, p_projh, p_kph, p_kmax);

    // kv partials: fp16 split-K=4 over K=4096 (each 1024)
    hgemm_bh<true, false, float, 4><<<dim3(1, 2, 256), 256>>>(
        p_kph, (size_t)16777216, (size_t)256, 4096,
        p_vh,  (size_t)4194304,  (size_t)64,  1024,
        p_kvp, (size_t)(16 * 16384), (size_t)16384, 64, (size_t)KVN,
        nullptr, 0, 0, 0,
        256, 64, 1024);
    k_kvred<<<(KVN / 4 + 255) / 256, 256>>>((const float4*)p_kvp, (__half2*)p_kvh);

    k_ksum<<<dim3(8, 64), 256>>>(p_kph, p_ksum);
    k_denom<<<NR / 8, 256>>>(p_qph, p_ksum, p_den);

    // attn = (qp @ kv) / denom : fp16 -> fp16
    hgemm_bh<false, true, __half, 1><<<dim3(1, 32, 64), 256>>>(
        p_qph, (size_t)16777216, (size_t)256, 4096,
        p_kvh, (size_t)(16 * 16384), (size_t)16384, 64,
        p_attnh, (size_t)4194304, (size_t)64, 1024, (size_t)0,
        p_den,  (size_t)65536,   (size_t)1,  16,
        4096, 64, 256);

    // attn_out = attn @ wo^T -> fp32 tmp
    hgemm<EPI_NONE, float, false><<<dim3(8, 128), 256>>>(
        p_attnh, p_woT, nullptr, p_tmp, nullptr, nullptr, NT, 1024, 1024);

    // out1 = LN(x + attn_out) -> fp32 + fp16
    k_ln<true><<<NT, 256>>>(p_tmp, x, ln1g, ln1b, p_out1, p_out1h);

    // FFN
    hgemm<EPI_BIAS_ELU, __half, false><<<dim3(32, 128), 256>>>(
        p_out1h, p_w1T, b1, p_hh, nullptr, nullptr, NT, DFF, 1024);
    hgemm<EPI_BIAS, float, false><<<dim3(8, 128), 256>>>(
        p_hh, p_w2T, b2, p_tmp, nullptr, nullptr, NT, 1024, DFF);

    // out2 = LN(out1 + ffn)
    k_ln<false><<<NT, 256>>>(p_tmp, p_out1, ln2g, ln2b, out, nullptr);
}

// round 15
// speedup vs baseline: 1.2620x; 1.1191x over previous
#include <cuda_runtime.h>
#include <cuda_fp16.h>
#include <math.h>
#include <stdint.h>

#define BB   4
#define LL   4096
#define DD   1024
#define HH   16
#define DHH  64
#define MMF  256
#define DFF  4096
#define NT   (BB*LL)      /* 16384 tokens  */
#define NR   (NT*HH)      /* 262144 (t,h) rows */
#define KVN  (BB*HH*MMF*DHH)   /* 1048576 */

// ---------------- scratch (device globals; no allocation allowed) ----------
__device__ float  g_kvp  [4*KVN];
__device__ float  g_ksum [BB*HH*MMF];
__device__ float  g_den  [NR];
__device__ float  g_tmp  [(size_t)NT*DD];
__device__ float  g_out1 [(size_t)NT*DD];
__device__ unsigned g_kmax;
// fp16 buffers
__device__ __half g_xh   [(size_t)NT*DD];
__device__ __half g_qh   [(size_t)NT*DD];
__device__ __half g_kh   [(size_t)NT*DD];
__device__ __half g_vh   [(size_t)NT*DD];
__device__ __half g_qph  [(size_t)NR*MMF];
__device__ __half g_kph  [(size_t)NR*MMF];
__device__ __half g_kvh  [KVN];
__device__ __half g_out1h[(size_t)NT*DD];
__device__ __half g_attnh[(size_t)NT*DD];
__device__ __half g_hh   [(size_t)NT*DFF];
__device__ __half g_projh[MMF*DHH];
__device__ __half g_wqkvT[3*DD*DD];             // packed [3072][1024]
__device__ __half g_woT  [DD*DD];
__device__ __half g_w1T  [(size_t)DFF*DD];
__device__ __half g_w2T  [(size_t)DD*DFF];

enum { EPI_NONE = 0, EPI_BIAS = 1, EPI_BIAS_ELU = 2 };
enum { DD_Q = 0, DD_KMAX = 1, DD_KEXP = 2 };

// ---------------- helpers ----------------------------------------------------
__device__ __forceinline__ void mma_f16(float* d, const unsigned* a,
                                        const unsigned* b)
{
    asm volatile(
        "mma.sync.aligned.m16n8k16.row.col.f32.f16.f16.f32 "
        "{%0,%1,%2,%3}, {%4,%5,%6,%7}, {%8,%9}, {%0,%1,%2,%3};\n"
        : "+f"(d[0]), "+f"(d[1]), "+f"(d[2]), "+f"(d[3])
        : "r"(a[0]), "r"(a[1]), "r"(a[2]), "r"(a[3]),
          "r"(b[0]), "r"(b[1]));
}

__device__ __forceinline__ void ldsm_x4(unsigned* r, unsigned addr)
{
    asm volatile("ldmatrix.sync.aligned.m8n8.x4.shared.b16 {%0,%1,%2,%3}, [%4];"
        : "=r"(r[0]), "=r"(r[1]), "=r"(r[2]), "=r"(r[3]) : "r"(addr));
}

__device__ __forceinline__ void ldsm_x4t(unsigned* r, unsigned addr)
{
    asm volatile("ldmatrix.sync.aligned.m8n8.x4.trans.shared.b16 {%0,%1,%2,%3}, [%4];"
        : "=r"(r[0]), "=r"(r[1]), "=r"(r[2]), "=r"(r[3]) : "r"(addr));
}

__device__ __forceinline__ void cpa16(unsigned dst, const void* src)
{
    asm volatile("cp.async.cg.shared.global [%0], [%1], 16;" :: "r"(dst), "l"(src));
}
__device__ __forceinline__ void cpa_commit()
{
    asm volatile("cp.async.commit_group;");
}
template<int N> __device__ __forceinline__ void cpa_wait()
{
    asm volatile("cp.async.wait_group %0;" :: "n"(N));
}

__device__ __forceinline__ float unflip(unsigned u)
{
    return __uint_as_float((u & 0x80000000u) ? (u ^ 0x80000000u) : ~u);
}

__device__ __forceinline__ __half2 h2ex2(__half2 x)
{
    unsigned u = *(unsigned*)&x, y;
    asm("ex2.approx.f16x2 %0, %1;" : "=r"(y) : "r"(u));
    return *(__half2*)&y;
}

// ---------------- fp16 tensor-core GEMM: C[M,N] = A[M,K] @ B^T ----------------
// 128x128 CTA tile, 256 threads = 8 warps (4m x 2n), warp tile 32x64,
// ldmatrix fragments. NEW: 3-stage cp.async pipeline (dynamic smem, 60KB),
// wait_group<1> -> 2 iterations of load slack; one __syncthreads per iter.
// SPLIT3: route 1024-col slices of N to C/C2/C3 (fp16, stride 1024).
#define HS 40
#define HBUF (128 * HS)               /* halves per operand per stage */
#define HBUFB (HBUF * 2)              /* bytes */
#define T5SMEM (3 * 2 * HBUFB)        /* 61440 bytes dynamic */

template<int EPI, typename OutT, bool SPLIT3>
__global__ __launch_bounds__(256, 2)
void hgemm(const __half* __restrict__ A, const __half* __restrict__ B,
           const float* __restrict__ bias, OutT* __restrict__ C,
           __half* __restrict__ C2, __half* __restrict__ C3,
           int M, int N, int K)
{
    extern __shared__ __align__(16) __half smem[];
    __half* As = smem;                  // 3 * HBUF
    __half* Bs = smem + 3 * HBUF;       // 3 * HBUF

    const int tid  = threadIdx.x;
    const int wid  = tid >> 5;
    const int lane = tid & 31;
    const int wm   = (wid >> 1) * 32;
    const int wn   = (wid & 1)  * 64;
    const size_t m0 = (size_t)blockIdx.y * 128;
    const int    n0 = blockIdx.x * 128;

    const int ar0 = tid >> 2,          aq0 = (tid & 3) << 3;
    const int ar1 = (tid + 256) >> 2,  aq1 = ((tid + 256) & 3) << 3;

    const int matid = lane >> 3, rowin = lane & 7;
    const unsigned sAb = (unsigned)__cvta_generic_to_shared(As);
    const unsigned sBb = (unsigned)__cvta_generic_to_shared(Bs);
    unsigned aoff[2], boff[4];
#pragma unroll
    for (int mt = 0; mt < 2; mt++)
        aoff[mt] = sAb + (unsigned)(((wm + mt * 16 + rowin + ((matid & 1) << 3)) * HS
                                     + ((matid & 2) << 2)) << 1);
#pragma unroll
    for (int p = 0; p < 4; p++)
        boff[p] = sBb + (unsigned)(((wn + ((p << 1) + ((matid >> 1) & 1)) * 8 + rowin) * HS
                                     + ((matid & 1) << 3)) << 1);

    // per-thread cp.async smem destinations (stage 0; add s*HBUFB)
    const unsigned dA0 = sAb + (unsigned)((ar0 * HS + aq0) << 1);
    const unsigned dA1 = sAb + (unsigned)((ar1 * HS + aq1) << 1);
    const unsigned dB0 = sBb + (unsigned)((ar0 * HS + aq0) << 1);
    const unsigned dB1 = sBb + (unsigned)((ar1 * HS + aq1) << 1);

    float acc[2][8][4];
#pragma unroll
    for (int mt = 0; mt < 2; mt++)
#pragma unroll
        for (int nt = 0; nt < 8; nt++)
#pragma unroll
            for (int i = 0; i < 4; i++) acc[mt][nt][i] = 0.f;

    const int iters = K >> 5;

    auto issue = [&](int s, int k0) {
        const unsigned so = (unsigned)(s * HBUFB);
        cpa16(dA0 + so, A + (m0 + ar0) * K + k0 + aq0);
        cpa16(dA1 + so, A + (m0 + ar1) * K + k0 + aq1);
        cpa16(dB0 + so, B + (size_t)(n0 + ar0) * K + k0 + aq0);
        cpa16(dB1 + so, B + (size_t)(n0 + ar1) * K + k0 + aq1);
        cpa_commit();
    };

    issue(0, 0);
    if (iters > 1) issue(1, 32);

    int s = 0, s2 = (iters > 1) ? 2 : 1;
    for (int it = 0; it < iters; it++) {
        cpa_wait<1>();
        __syncthreads();

        const unsigned ab = (unsigned)(s * HBUFB);
#pragma unroll
        for (int ks = 0; ks < 2; ks++) {
            const unsigned cb = ab + (unsigned)(ks << 5);
            unsigned af[2][4], bf[4][4];
#pragma unroll
            for (int mt = 0; mt < 2; mt++) ldsm_x4(af[mt], aoff[mt] + cb);
#pragma unroll
            for (int p = 0; p < 4; p++)   ldsm_x4(bf[p],  boff[p]  + cb);
#pragma unroll
            for (int mt = 0; mt < 2; mt++)
#pragma unroll
                for (int p = 0; p < 4; p++) {
                    mma_f16(acc[mt][2 * p],     af[mt], &bf[p][0]);
                    mma_f16(acc[mt][2 * p + 1], af[mt], &bf[p][2]);
                }
        }

        if (it + 2 < iters) {
            issue(s2, (it + 2) << 5);
            s2 = (s2 + 1 == 3) ? 0 : s2 + 1;
        }
        s = (s + 1 == 3) ? 0 : s + 1;
        __syncthreads();
    }

    // SPLIT3 routing (CTA-constant)
    __half* Ch = nullptr;
    if (SPLIT3) {
        const int slice = n0 >> 10;
        Ch = (slice == 0) ? (__half*)C : ((slice == 1) ? C2 : C3);
    }

#pragma unroll
    for (int mt = 0; mt < 2; mt++) {
#pragma unroll
        for (int nt = 0; nt < 8; nt++) {
            size_t row = m0 + wm + mt * 16 + (lane >> 2);
            int gcol = n0 + wn + nt * 8 + ((lane & 3) << 1);
            float2 lo = make_float2(acc[mt][nt][0], acc[mt][nt][1]);
            float2 hi = make_float2(acc[mt][nt][2], acc[mt][nt][3]);
            if (EPI == EPI_BIAS || EPI == EPI_BIAS_ELU) {
                float2 bb = *(const float2*)(bias + gcol);
                lo.x += bb.x; lo.y += bb.y;
                hi.x += bb.x; hi.y += bb.y;
            }
            if (EPI == EPI_BIAS_ELU) {
                lo.x = lo.x > 0.f ? lo.x : expm1f(lo.x);
                lo.y = lo.y > 0.f ? lo.y : expm1f(lo.y);
                hi.x = hi.x > 0.f ? hi.x : expm1f(hi.x);
                hi.y = hi.y > 0.f ? hi.y : expm1f(hi.y);
            }
            if (SPLIT3) {
                int col = gcol & 1023;
                *(__half2*)(Ch + row * 1024 + col)       = __floats2half2_rn(lo.x, lo.y);
                *(__half2*)(Ch + (row + 8) * 1024 + col) = __floats2half2_rn(hi.x, hi.y);
            } else if (sizeof(OutT) == 2) {
                *(__half2*)((__half*)C + row * N + gcol)       = __floats2half2_rn(lo.x, lo.y);
                *(__half2*)((__half*)C + (row + 8) * N + gcol) = __floats2half2_rn(hi.x, hi.y);
            } else {
                *(float2*)((float*)C + row * N + gcol)       = lo;
                *(float2*)((float*)C + (row + 8) * N + gcol) = hi;
            }
        }
    }
}

// ---------------- fused dd GEMM + Performer feature map -----------------------
// (unchanged — proven)
#define DS 72

template<int MODE>
__global__ __launch_bounds__(256, 2)
void ddexp(const __half* __restrict__ A, const __half* __restrict__ Bp,
           __half* __restrict__ outp, unsigned* __restrict__ gmax)
{
    __shared__ __align__(16) __half As[64 * DS];
    __shared__ __align__(16) __half Bs[256 * DS];
    __shared__ float sdiag[64];
    __shared__ float srmax[4][64];

    const int tid  = threadIdx.x;
    const int wid  = tid >> 5;
    const int lane = tid & 31;
    const int wm   = (wid >> 2) * 32;
    const int wn   = (wid & 3)  * 64;
    const size_t m0 = (size_t)blockIdx.x * 64;

#pragma unroll
    for (int i = 0; i < 2; i++) {
        int c = tid + i * 256;
        int r = c >> 3, cc = (c & 7) << 3;
        *(uint4*)&As[r * DS + cc] = *(const uint4*)(A + (m0 + r) * 64 + cc);
    }
#pragma unroll
    for (int i = 0; i < 8; i++) {
        int c = tid + i * 256;
        int r = c >> 3, cc = (c & 7) << 3;
        *(uint4*)&Bs[r * DS + cc] = *(const uint4*)(Bp + (size_t)r * 64 + cc);
    }
    __syncthreads();

    if (MODE != DD_KMAX && tid < 64) {
        const __half2* row = (const __half2*)&As[tid * DS];
        float ss = 0.f;
#pragma unroll
        for (int i = 0; i < 32; i++) {
            float2 v = __half22float2(row[i]);
            ss += v.x * v.x + v.y * v.y;
        }
        sdiag[tid] = ss;
    }

    const int matid = lane >> 3, rowin = lane & 7;
    const unsigned sA = (unsigned)__cvta_generic_to_shared(As);
    const unsigned sB = (unsigned)__cvta_generic_to_shared(Bs);
    unsigned aoff[2], boff[4];
#pragma unroll
    for (int mt = 0; mt < 2; mt++)
        aoff[mt] = sA + (unsigned)(((wm + mt * 16 + rowin + ((matid & 1) << 3)) * DS
                                    + ((matid & 2) << 2)) << 1);
#pragma unroll
    for (int p = 0; p < 4; p++)
        boff[p] = sB + (unsigned)(((wn + ((p << 1) + ((matid >> 1) & 1)) * 8 + rowin) * DS
                                    + ((matid & 1) << 3)) << 1);

    float acc[2][8][4];
#pragma unroll
    for (int mt = 0; mt < 2; mt++)
#pragma unroll
        for (int nt = 0; nt < 8; nt++)
#pragma unroll
            for (int i = 0; i < 4; i++) acc[mt][nt][i] = 0.f;

#pragma unroll
    for (int ks = 0; ks < 4; ks++) {
        const unsigned cb = (unsigned)(ks << 5);
        unsigned af[2][4], bf[4][4];
#pragma unroll
        for (int mt = 0; mt < 2; mt++) ldsm_x4(af[mt], aoff[mt] + cb);
#pragma unroll
        for (int p = 0; p < 4; p++)   ldsm_x4(bf[p],  boff[p]  + cb);
#pragma unroll
        for (int mt = 0; mt < 2; mt++)
#pragma unroll
            for (int p = 0; p < 4; p++) {
                mma_f16(acc[mt][2 * p],     af[mt], &bf[p][0]);
                mma_f16(acc[mt][2 * p + 1], af[mt], &bf[p][2]);
            }
    }

    if (MODE == DD_KMAX) {
        float mx = -3.4e38f;
#pragma unroll
        for (int mt = 0; mt < 2; mt++)
#pragma unroll
            for (int nt = 0; nt < 8; nt++)
#pragma unroll
                for (int i = 0; i < 4; i++) mx = fmaxf(mx, acc[mt][nt][i]);
#pragma unroll
        for (int o = 16; o; o >>= 1) mx = fmaxf(mx, __shfl_xor_sync(0xffffffffu, mx, o));
        if (lane == 0) {
            unsigned u = __float_as_uint(mx);
            u = (u & 0x80000000u) ? ~u : (u | 0x80000000u);
            atomicMax(gmax, u);
        }
        return;
    }

    if (MODE == DD_Q) {
#pragma unroll
        for (int mt = 0; mt < 2; mt++) {
            float m0v = -3.4e38f, m1v = -3.4e38f;
#pragma unroll
            for (int nt = 0; nt < 8; nt++) {
                m0v = fmaxf(m0v, fmaxf(acc[mt][nt][0], acc[mt][nt][1]));
                m1v = fmaxf(m1v, fmaxf(acc[mt][nt][2], acc[mt][nt][3]));
            }
#pragma unroll
            for (int o = 1; o <= 2; o <<= 1) {
                m0v = fmaxf(m0v, __shfl_xor_sync(0xffffffffu, m0v, o));
                m1v = fmaxf(m1v, __shfl_xor_sync(0xffffffffu, m1v, o));
            }
            if ((lane & 3) == 0) {
                srmax[wid & 3][wm + mt * 16 + (lane >> 2)]     = m0v;
                srmax[wid & 3][wm + mt * 16 + 8 + (lane >> 2)] = m1v;
            }
        }
    }
    __syncthreads();

    const float gm = (MODE == DD_KEXP) ? unflip(*gmax) : 0.f;
    const float L2E = 1.4426950408889634f;
    const __half2 eps2 = __float2half2_rn(1e-6f);
    const __half2 rat2 = __float2half2_rn(0.0625f);

#pragma unroll
    for (int mt = 0; mt < 2; mt++) {
        const int r0 = wm + mt * 16 + (lane >> 2);
        const int r1 = r0 + 8;
        float c0, c1;
        if (MODE == DD_Q) {
            float rm0 = fmaxf(fmaxf(srmax[0][r0], srmax[1][r0]),
                              fmaxf(srmax[2][r0], srmax[3][r0]));
            float rm1 = fmaxf(fmaxf(srmax[0][r1], srmax[1][r1]),
                              fmaxf(srmax[2][r1], srmax[3][r1]));
            c0 = 0.0625f * sdiag[r0] + rm0;
            c1 = 0.0625f * sdiag[r1] + rm1;
        } else {
            c0 = 0.0625f * sdiag[r0] + gm;
            c1 = 0.0625f * sdiag[r1] + gm;
        }
        const float c0l = c0 * L2E, c1l = c1 * L2E;
#pragma unroll
        for (int nt = 0; nt < 8; nt++) {
            const int col = wn + nt * 8 + ((lane & 3) << 1);
            __half2 t01 = __floats2half2_rn(fmaf(acc[mt][nt][0], L2E, -c0l),
                                            fmaf(acc[mt][nt][1], L2E, -c0l));
            __half2 t23 = __floats2half2_rn(fmaf(acc[mt][nt][2], L2E, -c1l),
                                            fmaf(acc[mt][nt][3], L2E, -c1l));
            __half2 e01 = __hmul2(__hadd2(h2ex2(t01), eps2), rat2);
            __half2 e23 = __hmul2(__hadd2(h2ex2(t23), eps2), rat2);
            *(__half2*)(outp + (m0 + r0) * 256 + col) = e01;
            *(__half2*)(outp + (m0 + r1) * 256 + col) = e23;
        }
    }
}

// ------------- fp16 batched strided GEMM over (b,h), optional split-K --------
// (unchanged — proven)
#define BAS 136
#define NAS 40
#define BBS 72

template<bool TRANSA, bool DIV, typename OutT, int NSPLIT>
__global__ __launch_bounds__(256, 2)
void hgemm_bh(const __half* __restrict__ A, size_t sAb, size_t sAh, int lda,
              const __half* __restrict__ B, size_t sBb, size_t sBh, int ldb,
              OutT* __restrict__ C, size_t sCb, size_t sCh, int ldc, size_t sCsplit,
              const float* __restrict__ aux, size_t sXb, size_t sXh, int ldx,
              int M, int N, int K)
{
    constexpr int ABUFH = TRANSA ? (32 * BAS) : (128 * NAS);
    constexpr int BBUFH = 32 * BBS;
    __shared__ __align__(16) __half As[2 * ABUFH];
    __shared__ __align__(16) __half Bs[2 * BBUFH];

    const int z     = blockIdx.z;
    const int split = (NSPLIT > 1) ? (z >> 6) : 0;
    const int zz    = (NSPLIT > 1) ? (z & 63) : z;
    const int zb = zz >> 4, zh = zz & 15;
    const __half* Ab = A + (size_t)zb * sAb + (size_t)zh * sAh;
    const __half* Bb = B + (size_t)zb * sBb + (size_t)zh * sBh;
    OutT*         Cb = C + (size_t)zb * sCb + (size_t)zh * sCh
                         + (size_t)split * sCsplit;
    if (NSPLIT > 1) {
        Ab += (size_t)split * K * lda;
        Bb += (size_t)split * K * ldb;
    }

    const int tid  = threadIdx.x;
    const int wid  = tid >> 5;
    const int lane = tid & 31;
    const int wm   = (wid >> 1) * 32;
    const int wn   = (wid & 1)  * 32;
    const int m0   = blockIdx.y * 128;

    const int matid = lane >> 3, rowin = lane & 7;
    const unsigned sAs = (unsigned)__cvta_generic_to_shared(As);
    const unsigned sBs = (unsigned)__cvta_generic_to_shared(Bs);

    unsigned aoff[2], boff[2];
#pragma unroll
    for (int mt = 0; mt < 2; mt++) {
        if (TRANSA)
            aoff[mt] = sAs + (unsigned)(((rowin + ((matid >> 1) << 3)) * BAS
                                         + wm + mt * 16 + ((matid & 1) << 3)) << 1);
        else
            aoff[mt] = sAs + (unsigned)(((wm + mt * 16 + rowin + ((matid & 1) << 3)) * NAS
                                         + ((matid & 2) << 2)) << 1);
    }
#pragma unroll
    for (int p = 0; p < 2; p++)
        boff[p] = sBs + (unsigned)(((rowin + ((matid & 1) << 3)) * BBS
                                    + wn + (p << 4) + ((matid >> 1) << 3)) << 1);

    const int ta_kr = tid >> 4, ta_mc = (tid & 15) << 3;
    const int na_r0 = tid >> 2, na_k0 = (tid & 3) << 3;
    const int b_kr  = tid >> 3, b_nc  = (tid & 7) << 3;

    uint4 ra0, ra1, rb;
    float acc[2][4][4];
#pragma unroll
    for (int mt = 0; mt < 2; mt++)
#pragma unroll
        for (int nt = 0; nt < 4; nt++)
#pragma unroll
            for (int i = 0; i < 4; i++) acc[mt][nt][i] = 0.f;

    const int iters = K >> 5;

    auto ld = [&](int k0) {
        if (TRANSA) {
            ra0 = *(const uint4*)(Ab + (size_t)(k0 + ta_kr)      * lda + m0 + ta_mc);
            ra1 = *(const uint4*)(Ab + (size_t)(k0 + ta_kr + 16) * lda + m0 + ta_mc);
        } else {
            ra0 = *(const uint4*)(Ab + (size_t)(m0 + na_r0)      * lda + k0 + na_k0);
            ra1 = *(const uint4*)(Ab + (size_t)(m0 + na_r0 + 64) * lda + k0 + na_k0);
        }
        rb = *(const uint4*)(Bb + (size_t)(k0 + b_kr) * ldb + b_nc);
    };
    auto st = [&](int s) {
        __half* as = As + s * ABUFH;
        __half* bs = Bs + s * BBUFH;
        if (TRANSA) {
            *(uint4*)&as[ta_kr * BAS + ta_mc]        = ra0;
            *(uint4*)&as[(ta_kr + 16) * BAS + ta_mc] = ra1;
        } else {
            *(uint4*)&as[na_r0 * NAS + na_k0]        = ra0;
            *(uint4*)&as[(na_r0 + 64) * NAS + na_k0] = ra1;
        }
        *(uint4*)&bs[b_kr * BBS + b_nc] = rb;
    };

    ld(0); st(0);
    __syncthreads();

    for (int it = 0; it < iters; it++) {
        const bool more = (it + 1 < iters);
        if (more) ld((it + 1) << 5);

        const unsigned ab = (unsigned)((it & 1) * (ABUFH * 2));
        const unsigned bb = (unsigned)((it & 1) * (BBUFH * 2));
#pragma unroll
        for (int ks = 0; ks < 2; ks++) {
            const unsigned aks = TRANSA ? (unsigned)(ks * 16 * BAS * 2) : (unsigned)(ks << 5);
            const unsigned bks = (unsigned)(ks * 16 * BBS * 2);
            unsigned af[2][4], bf[2][4];
#pragma unroll
            for (int mt = 0; mt < 2; mt++) {
                if (TRANSA) ldsm_x4t(af[mt], aoff[mt] + ab + aks);
                else        ldsm_x4 (af[mt], aoff[mt] + ab + aks);
            }
#pragma unroll
            for (int p = 0; p < 2; p++) ldsm_x4t(bf[p], boff[p] + bb + bks);
#pragma unroll
            for (int mt = 0; mt < 2; mt++)
#pragma unroll
                for (int p = 0; p < 2; p++) {
                    mma_f16(acc[mt][2 * p],     af[mt], &bf[p][0]);
                    mma_f16(acc[mt][2 * p + 1], af[mt], &bf[p][2]);
                }
        }

        if (more) st((it + 1) & 1);
        __syncthreads();
    }

#pragma unroll
    for (int mt = 0; mt < 2; mt++) {
        int row = m0 + wm + mt * 16 + (lane >> 2);
        float dv0 = 1.f, dv1 = 1.f;
        if (DIV) {
            dv0 = 1.f / aux[(size_t)zb * sXb + (size_t)zh * sXh + (size_t)row * ldx];
            dv1 = 1.f / aux[(size_t)zb * sXb + (size_t)zh * sXh + (size_t)(row + 8) * ldx];
        }
#pragma unroll
        for (int nt = 0; nt < 4; nt++) {
            int col = wn + nt * 8 + ((lane & 3) << 1);
            float2 lo = make_float2(acc[mt][nt][0] * dv0, acc[mt][nt][1] * dv0);
            float2 hi = make_float2(acc[mt][nt][2] * dv1, acc[mt][nt][3] * dv1);
            if (sizeof(OutT) == 2) {
                *(__half2*)((__half*)Cb + (size_t)row * ldc + col)       = __floats2half2_rn(lo.x, lo.y);
                *(__half2*)((__half*)Cb + (size_t)(row + 8) * ldc + col) = __floats2half2_rn(hi.x, hi.y);
            } else {
                *(float2*)((float*)Cb + (size_t)row * ldc + col)       = lo;
                *(float2*)((float*)Cb + (size_t)(row + 8) * ldc + col) = hi;
            }
        }
    }
}

// ---------------- small helper kernels --------------------------------------
__global__ void k_half4(const float4* __restrict__ in, __half2* __restrict__ out,
                        int n4)
{
    int i = blockIdx.x * 256 + threadIdx.x;
    if (i < n4) {
        float4 v = in[i];
        out[2 * i]     = __floats2half2_rn(v.x, v.y);
        out[2 * i + 1] = __floats2half2_rn(v.z, v.w);
    }
}

__global__ void k_transH(const float* __restrict__ in, __half* __restrict__ out,
                         int K, int N)
{
    __shared__ float t[32][33];
    const int n0 = blockIdx.x * 32, k0 = blockIdx.y * 32;
#pragma unroll
    for (int i = 0; i < 4; i++) {
        int kk = threadIdx.y + i * 8;
        t[kk][threadIdx.x] = in[(size_t)(k0 + kk) * N + n0 + threadIdx.x];
    }
    __syncthreads();
#pragma unroll
    for (int i = 0; i < 4; i++) {
        int nn = threadIdx.y + i * 8;
        out[(size_t)(n0 + nn) * K + k0 + threadIdx.x] = __float2half(t[threadIdx.x][nn]);
    }
}

__global__ void k_projH(const float* __restrict__ proj, __half* __restrict__ ph)
{
    int i = blockIdx.x * 256 + threadIdx.x;
    if (i < MMF * DHH)
        ph[i] = __float2half(proj[i] * 0.35355339059327373f);
}

__global__ void k_kvred(const float4* __restrict__ part, __half2* __restrict__ kv)
{
    int i = blockIdx.x * 256 + threadIdx.x;
    if (i < KVN / 4) {
        float4 a = part[i];
        float4 b = part[i + KVN / 4];
        float4 c = part[i + 2 * (KVN / 4)];
        float4 d = part[i + 3 * (KVN / 4)];
        kv[2 * i]     = __floats2half2_rn(a.x + b.x + c.x + d.x, a.y + b.y + c.y + d.y);
        kv[2 * i + 1] = __floats2half2_rn(a.z + b.z + c.z + d.z, a.w + b.w + c.w + d.w);
    }
}

__global__ void k_ksum(const __half* __restrict__ kp, float* __restrict__ ksum)
{
    int z = blockIdx.y;
    int b = z >> 4, h = z & 15;
    int m = threadIdx.x;
    size_t base = (size_t)b * 16777216 + (size_t)h * 256 + m;
    float s = 0.f;
    int l0 = blockIdx.x * 512;
    for (int l = l0; l < l0 + 512; l++) s += __half2float(kp[base + (size_t)l * 4096]);
    atomicAdd(&ksum[z * 256 + m], s);
}

__global__ void k_denom(const __half* __restrict__ qp, const float* __restrict__ ksum,
                        float* __restrict__ den)
{
    size_t w   = ((size_t)blockIdx.x * blockDim.x + threadIdx.x) >> 5;
    int   lane = threadIdx.x & 31;
    int   b    = (int)(w >> 16);
    int   h    = (int)(w & 15);
    const __half2* row = (const __half2*)(qp + w * 256);
    const float4*  ks  = (const float4*)(ksum + ((size_t)b * 16 + h) * 256);
    float4 k0 = ks[lane * 2], k1 = ks[lane * 2 + 1];
    float2 a0 = __half22float2(row[lane * 4]);
    float2 a1 = __half22float2(row[lane * 4 + 1]);
    float2 a2 = __half22float2(row[lane * 4 + 2]);
    float2 a3 = __half22float2(row[lane * 4 + 3]);
    float s = a0.x * k0.x + a0.y * k0.y + a1.x * k0.z + a1.y * k0.w
            + a2.x * k1.x + a2.y * k1.y + a3.x * k1.z + a3.y * k1.w;
#pragma unroll
    for (int o = 16; o; o >>= 1) s += __shfl_xor_sync(0xffffffffu, s, o);
    if (lane == 0) den[w] = s;
}

template<bool WRITE_H>
__global__ void k_ln(const float* __restrict__ a, const float* __restrict__ r,
                     const float* __restrict__ g, const float* __restrict__ b,
                     float* __restrict__ out, __half* __restrict__ outh)
{
    const int row = blockIdx.x;
    const int t   = threadIdx.x;
    const size_t base = (size_t)row * 1024;
    float4 xa = *(const float4*)(a + base + t * 4);
    float4 xr = *(const float4*)(r + base + t * 4);
    float4 s  = make_float4(xa.x + xr.x, xa.y + xr.y, xa.z + xr.z, xa.w + xr.w);
    float sum = s.x + s.y + s.z + s.w;
    float sq  = s.x * s.x + s.y * s.y + s.z * s.z + s.w * s.w;
#pragma unroll
    for (int o = 16; o; o >>= 1) {
        sum += __shfl_xor_sync(0xffffffffu, sum, o);
        sq  += __shfl_xor_sync(0xffffffffu, sq,  o);
    }
    __shared__ float ssum[8], ssq[8];
    __shared__ float s_mu, s_inv;
    int w = t >> 5;
    if ((t & 31) == 0) { ssum[w] = sum; ssq[w] = sq; }
    __syncthreads();
    if (t == 0) {
        float ts = 0.f, tq = 0.f;
        for (int i = 0; i < 8; i++) { ts += ssum[i]; tq += ssq[i]; }
        float mu  = ts * (1.f / 1024.f);
        float var = tq * (1.f / 1024.f) - mu * mu;
        s_mu = mu;
        s_inv = rsqrtf(var + 1e-6f);
    }
    __syncthreads();
    float mu = s_mu, inv = s_inv;
    float4 gg = *(const float4*)(g + t * 4);
    float4 bb = *(const float4*)(b + t * 4);
    float4 o = make_float4((s.x - mu) * inv * gg.x + bb.x,
                           (s.y - mu) * inv * gg.y + bb.y,
                           (s.z - mu) * inv * gg.z + bb.z,
                           (s.w - mu) * inv * gg.w + bb.w);
    *(float4*)(out + base + t * 4) = o;
    if (WRITE_H) {
        __half2* oh = (__half2*)(outh + base + t * 4);
        oh[0] = __floats2half2_rn(o.x, o.y);
        oh[1] = __floats2half2_rn(o.z, o.w);
    }
}

// ---------------- driver -----------------------------------------------------
extern "C" void kernel_launch(void* const* d_in, const int* in_sizes, int n_in,
                              void* d_out, int out_size)
{
    const float* x    = (const float*)d_in[0];
    const float* wq   = (const float*)d_in[1];
    const float* wk   = (const float*)d_in[2];
    const float* wv   = (const float*)d_in[3];
    const float* wo   = (const float*)d_in[4];
    const float* proj = (const float*)d_in[5];
    const float* ln1g = (const float*)d_in[6];
    const float* ln1b = (const float*)d_in[7];
    const float* ln2g = (const float*)d_in[8];
    const float* ln2b = (const float*)d_in[9];
    const float* w1   = (const float*)d_in[10];
    const float* b1   = (const float*)d_in[11];
    const float* w2   = (const float*)d_in[12];
    const float* b2   = (const float*)d_in[13];
    float* out = (float*)d_out;

    float *p_kvp, *p_ksum, *p_den, *p_tmp, *p_out1;
    __half *p_xh, *p_qh, *p_kh, *p_vh, *p_qph, *p_kph, *p_kvh;
    __half *p_out1h, *p_attnh, *p_hh, *p_projh;
    __half *p_wqkvT, *p_woT, *p_w1T, *p_w2T;
    unsigned* p_kmax;
    cudaGetSymbolAddress((void**)&p_kvp,   g_kvp);
    cudaGetSymbolAddress((void**)&p_ksum,  g_ksum);
    cudaGetSymbolAddress((void**)&p_den,   g_den);
    cudaGetSymbolAddress((void**)&p_tmp,   g_tmp);
    cudaGetSymbolAddress((void**)&p_out1,  g_out1);
    cudaGetSymbolAddress((void**)&p_kmax,  g_kmax);
    cudaGetSymbolAddress((void**)&p_xh,    g_xh);
    cudaGetSymbolAddress((void**)&p_qh,    g_qh);
    cudaGetSymbolAddress((void**)&p_kh,    g_kh);
    cudaGetSymbolAddress((void**)&p_vh,    g_vh);
    cudaGetSymbolAddress((void**)&p_qph,   g_qph);
    cudaGetSymbolAddress((void**)&p_kph,   g_kph);
    cudaGetSymbolAddress((void**)&p_kvh,   g_kvh);
    cudaGetSymbolAddress((void**)&p_out1h, g_out1h);
    cudaGetSymbolAddress((void**)&p_attnh, g_attnh);
    cudaGetSymbolAddress((void**)&p_hh,    g_hh);
    cudaGetSymbolAddress((void**)&p_projh, g_projh);
    cudaGetSymbolAddress((void**)&p_wqkvT, g_wqkvT);
    cudaGetSymbolAddress((void**)&p_woT,   g_woT);
    cudaGetSymbolAddress((void**)&p_w1T,   g_w1T);
    cudaGetSymbolAddress((void**)&p_w2T,   g_w2T);

    // allow 60KB dynamic smem for the 4 hgemm instantiations
    cudaFuncSetAttribute(hgemm<EPI_NONE, __half, true >, cudaFuncAttributeMaxDynamicSharedMemorySize, T5SMEM);
    cudaFuncSetAttribute(hgemm<EPI_NONE, float,  false>, cudaFuncAttributeMaxDynamicSharedMemorySize, T5SMEM);
    cudaFuncSetAttribute(hgemm<EPI_BIAS_ELU, __half, false>, cudaFuncAttributeMaxDynamicSharedMemorySize, T5SMEM);
    cudaFuncSetAttribute(hgemm<EPI_BIAS, float, false>, cudaFuncAttributeMaxDynamicSharedMemorySize, T5SMEM);

    // prep: x->fp16, pack transposed qkv weights into one [3072][1024] buffer
    k_half4<<<(NT * DD / 4 + 255) / 256, 256>>>((const float4*)x, (__half2*)p_xh, NT * DD / 4);
    k_transH<<<dim3(32, 32), dim3(32, 8)>>>(wq, p_wqkvT,               DD, DD);
    k_transH<<<dim3(32, 32), dim3(32, 8)>>>(wk, p_wqkvT + DD * DD,     DD, DD);
    k_transH<<<dim3(32, 32), dim3(32, 8)>>>(wv, p_wqkvT + 2 * DD * DD, DD, DD);
    k_projH<<<64, 256>>>(proj, p_projh);

    // merged QKV: one launch, slice-routed epilogue
    hgemm<EPI_NONE, __half, true><<<dim3(24, 128), 256, T5SMEM>>>(
        p_xh, p_wqkvT, nullptr, p_qh, p_kh, p_vh, NT, 3072, 1024);

    // remaining prep
    k_transH<<<dim3(32, 32),  dim3(32, 8)>>>(wo, p_woT, DD, DD);
    k_transH<<<dim3(128, 32), dim3(32, 8)>>>(w1, p_w1T, DD, DFF);
    k_transH<<<dim3(32, 128), dim3(32, 8)>>>(w2, p_w2T, DFF, DD);

    cudaMemsetAsync(p_kmax, 0, 4);
    cudaMemsetAsync(p_ksum, 0, BB * HH * MMF * sizeof(float));

    // fused dd + feature maps
    ddexp<DD_Q>   <<<NR / 64, 256>>>(p_qh, p_projh, p_qph, nullptr);
    ddexp<DD_KMAX><<<NR / 64, 256>>>(p_kh, p_projh, nullptr, p_kmax);
    ddexp<DD_KEXP><<<NR / 64, 256>>>(p_kh, p_projh, p_kph, p_kmax);

    // kv partials: fp16 split-K=4 over K=4096 (each 1024)
    hgemm_bh<true, false, float, 4><<<dim3(1, 2, 256), 256>>>(
        p_kph, (size_t)16777216, (size_t)256, 4096,
        p_vh,  (size_t)4194304,  (size_t)64,  1024,
        p_kvp, (size_t)(16 * 16384), (size_t)16384, 64, (size_t)KVN,
        nullptr, 0, 0, 0,
        256, 64, 1024);
    k_kvred<<<(KVN / 4 + 255) / 256, 256>>>((const float4*)p_kvp, (__half2*)p_kvh);

    k_ksum<<<dim3(8, 64), 256>>>(p_kph, p_ksum);
    k_denom<<<NR / 8, 256>>>(p_qph, p_ksum, p_den);

    // attn = (qp @ kv) / denom : fp16 -> fp16
    hgemm_bh<false, true, __half, 1><<<dim3(1, 32, 64), 256>>>(
        p_qph, (size_t)16777216, (size_t)256, 4096,
        p_kvh, (size_t)(16 * 16384), (size_t)16384, 64,
        p_attnh, (size_t)4194304, (size_t)64, 1024, (size_t)0,
        p_den,  (size_t)65536,   (size_t)1,  16,
        4096, 64, 256);

    // attn_out = attn @ wo^T -> fp32 tmp
    hgemm<EPI_NONE, float, false><<<dim3(8, 128), 256, T5SMEM>>>(
        p_attnh, p_woT, nullptr, p_tmp, nullptr, nullptr, NT, 1024, 1024);

    // out1 = LN(x + attn_out) -> fp32 + fp16
    k_ln<true><<<NT, 256>>>(p_tmp, x, ln1g, ln1b, p_out1, p_out1h);

    // FFN
    hgemm<EPI_BIAS_ELU, __half, false><<<dim3(32, 128), 256, T5SMEM>>>(
        p_out1h, p_w1T, b1, p_hh, nullptr, nullptr, NT, DFF, 1024);
    hgemm<EPI_BIAS, float, false><<<dim3(8, 128), 256, T5SMEM>>>(
        p_hh, p_w2T, b2, p_tmp, nullptr, nullptr, NT, 1024, DFF);

    // out2 = LN(out1 + ffn)
    k_ln<false><<<NT, 256>>>(p_tmp, p_out1, ln2g, ln2b, out, nullptr);
}

// round 17
// speedup vs baseline: 1.2814x; 1.0153x over previous
#include <cuda_runtime.h>
#include <cuda_fp16.h>
#include <math.h>
#include <stdint.h>

#define BB   4
#define LL   4096
#define DD   1024
#define HH   16
#define DHH  64
#define MMF  256
#define DFF  4096
#define NT   (BB*LL)      /* 16384 tokens  */
#define NR   (NT*HH)      /* 262144 (t,h) rows */
#define KVN  (BB*HH*MMF*DHH)   /* 1048576 */

// ---------------- scratch (device globals; no allocation allowed) ----------
__device__ float  g_kvp  [4*KVN];
__device__ float  g_ksum [BB*HH*MMF];
__device__ float  g_den  [NR];
__device__ float  g_tmp  [(size_t)NT*DD];
__device__ float  g_out1 [(size_t)NT*DD];
__device__ unsigned g_kmax;
// fp16 buffers
__device__ __half g_xh   [(size_t)NT*DD];
__device__ __half g_qh   [(size_t)NT*DD];
__device__ __half g_kh   [(size_t)NT*DD];
__device__ __half g_vh   [(size_t)NT*DD];
__device__ __half g_qph  [(size_t)NR*MMF];
__device__ __half g_kph  [(size_t)NR*MMF];
__device__ __half g_kvh  [KVN];
__device__ __half g_out1h[(size_t)NT*DD];
__device__ __half g_attnh[(size_t)NT*DD];
__device__ __half g_hh   [(size_t)NT*DFF];
__device__ __half g_projh[MMF*DHH];
__device__ __half g_wqkvT[3*DD*DD];             // packed [3072][1024]
__device__ __half g_woT  [DD*DD];
__device__ __half g_w1T  [(size_t)DFF*DD];
__device__ __half g_w2T  [(size_t)DD*DFF];

enum { EPI_NONE = 0, EPI_BIAS = 1, EPI_BIAS_ELU = 2 };
enum { DD_Q = 0, DD_KMAX = 1, DD_KEXP = 2 };

// ---------------- helpers ----------------------------------------------------
__device__ __forceinline__ void mma_f16(float* d, const unsigned* a,
                                        const unsigned* b)
{
    asm volatile(
        "mma.sync.aligned.m16n8k16.row.col.f32.f16.f16.f32 "
        "{%0,%1,%2,%3}, {%4,%5,%6,%7}, {%8,%9}, {%0,%1,%2,%3};\n"
        : "+f"(d[0]), "+f"(d[1]), "+f"(d[2]), "+f"(d[3])
        : "r"(a[0]), "r"(a[1]), "r"(a[2]), "r"(a[3]),
          "r"(b[0]), "r"(b[1]));
}

__device__ __forceinline__ void ldsm_x4(unsigned* r, unsigned addr)
{
    asm volatile("ldmatrix.sync.aligned.m8n8.x4.shared.b16 {%0,%1,%2,%3}, [%4];"
        : "=r"(r[0]), "=r"(r[1]), "=r"(r[2]), "=r"(r[3]) : "r"(addr));
}

__device__ __forceinline__ void ldsm_x4t(unsigned* r, unsigned addr)
{
    asm volatile("ldmatrix.sync.aligned.m8n8.x4.trans.shared.b16 {%0,%1,%2,%3}, [%4];"
        : "=r"(r[0]), "=r"(r[1]), "=r"(r[2]), "=r"(r[3]) : "r"(addr));
}

__device__ __forceinline__ void cpa16(unsigned dst, const void* src)
{
    asm volatile("cp.async.cg.shared.global [%0], [%1], 16;" :: "r"(dst), "l"(src));
}
__device__ __forceinline__ void cpa_commit()
{
    asm volatile("cp.async.commit_group;");
}
template<int N> __device__ __forceinline__ void cpa_wait()
{
    asm volatile("cp.async.wait_group %0;" :: "n"(N));
}

__device__ __forceinline__ float unflip(unsigned u)
{
    return __uint_as_float((u & 0x80000000u) ? (u ^ 0x80000000u) : ~u);
}

__device__ __forceinline__ __half2 h2ex2(__half2 x)
{
    unsigned u = *(unsigned*)&x, y;
    asm("ex2.approx.f16x2 %0, %1;" : "=r"(y) : "r"(u));
    return *(__half2*)&y;
}

// ---------------- fp16 tensor-core GEMM: C[M,N] = A[M,K] @ B^T ----------------
// 128x128 CTA tile, 256 threads = 8 warps (4m x 2n), warp tile 32x64,
// ldmatrix. 4-stage cp.async pipeline (80KB dynamic smem), wait_group<2>.
// FIX: commit an EMPTY group each iteration once real issues stop, so the
// wait_group accounting provably completes the consumed stage at the tail.
// SPLIT3: route 1024-col slices of N to C/C2/C3 (fp16, stride 1024).
#define HS 40
#define HBUF (128 * HS)               /* halves per operand per stage */
#define HBUFB (HBUF * 2)              /* bytes */
#define NSTG 4
#define T5SMEM (NSTG * 2 * HBUFB)     /* 81920 bytes dynamic */

template<int EPI, typename OutT, bool SPLIT3>
__global__ __launch_bounds__(256, 2)
void hgemm(const __half* __restrict__ A, const __half* __restrict__ B,
           const float* __restrict__ bias, OutT* __restrict__ C,
           __half* __restrict__ C2, __half* __restrict__ C3,
           int M, int N, int K)
{
    extern __shared__ __align__(16) __half smem[];
    __half* As = smem;                   // NSTG * HBUF
    __half* Bs = smem + NSTG * HBUF;     // NSTG * HBUF

    const int tid  = threadIdx.x;
    const int wid  = tid >> 5;
    const int lane = tid & 31;
    const int wm   = (wid >> 1) * 32;
    const int wn   = (wid & 1)  * 64;
    const size_t m0 = (size_t)blockIdx.y * 128;
    const int    n0 = blockIdx.x * 128;

    const int ar0 = tid >> 2,          aq0 = (tid & 3) << 3;
    const int ar1 = (tid + 256) >> 2,  aq1 = ((tid + 256) & 3) << 3;

    const int matid = lane >> 3, rowin = lane & 7;
    const unsigned sAb = (unsigned)__cvta_generic_to_shared(As);
    const unsigned sBb = (unsigned)__cvta_generic_to_shared(Bs);
    unsigned aoff[2], boff[4];
#pragma unroll
    for (int mt = 0; mt < 2; mt++)
        aoff[mt] = sAb + (unsigned)(((wm + mt * 16 + rowin + ((matid & 1) << 3)) * HS
                                     + ((matid & 2) << 2)) << 1);
#pragma unroll
    for (int p = 0; p < 4; p++)
        boff[p] = sBb + (unsigned)(((wn + ((p << 1) + ((matid >> 1) & 1)) * 8 + rowin) * HS
                                     + ((matid & 1) << 3)) << 1);

    const unsigned dA0 = sAb + (unsigned)((ar0 * HS + aq0) << 1);
    const unsigned dA1 = sAb + (unsigned)((ar1 * HS + aq1) << 1);
    const unsigned dB0 = sBb + (unsigned)((ar0 * HS + aq0) << 1);
    const unsigned dB1 = sBb + (unsigned)((ar1 * HS + aq1) << 1);

    float acc[2][8][4];
#pragma unroll
    for (int mt = 0; mt < 2; mt++)
#pragma unroll
        for (int nt = 0; nt < 8; nt++)
#pragma unroll
            for (int i = 0; i < 4; i++) acc[mt][nt][i] = 0.f;

    const int iters = K >> 5;

    auto issue = [&](int s, int k0) {
        const unsigned so = (unsigned)(s * HBUFB);
        cpa16(dA0 + so, A + (m0 + ar0) * K + k0 + aq0);
        cpa16(dA1 + so, A + (m0 + ar1) * K + k0 + aq1);
        cpa16(dB0 + so, B + (size_t)(n0 + ar0) * K + k0 + aq0);
        cpa16(dB1 + so, B + (size_t)(n0 + ar1) * K + k0 + aq1);
        cpa_commit();
    };

    issue(0, 0);
    if (iters > 1) issue(1, 32); else cpa_commit();
    if (iters > 2) issue(2, 64); else cpa_commit();

    int s = 0, s2 = 3 & (NSTG - 1);
    for (int it = 0; it < iters; it++) {
        cpa_wait<2>();
        __syncthreads();

        const unsigned ab = (unsigned)(s * HBUFB);
#pragma unroll
        for (int ks = 0; ks < 2; ks++) {
            const unsigned cb = ab + (unsigned)(ks << 5);
            unsigned af[2][4], bf[4][4];
#pragma unroll
            for (int mt = 0; mt < 2; mt++) ldsm_x4(af[mt], aoff[mt] + cb);
#pragma unroll
            for (int p = 0; p < 4; p++)   ldsm_x4(bf[p],  boff[p]  + cb);
#pragma unroll
            for (int mt = 0; mt < 2; mt++)
#pragma unroll
                for (int p = 0; p < 4; p++) {
                    mma_f16(acc[mt][2 * p],     af[mt], &bf[p][0]);
                    mma_f16(acc[mt][2 * p + 1], af[mt], &bf[p][2]);
                }
        }

        if (it + 3 < iters) {
            issue(s2, (it + 3) << 5);
            s2 = (s2 + 1 == NSTG) ? 0 : s2 + 1;
        } else {
            cpa_commit();   // empty group: keeps wait_group accounting exact
        }
        s = (s + 1 == NSTG) ? 0 : s + 1;
        __syncthreads();
    }

    __half* Ch = nullptr;
    if (SPLIT3) {
        const int slice = n0 >> 10;
        Ch = (slice == 0) ? (__half*)C : ((slice == 1) ? C2 : C3);
    }

#pragma unroll
    for (int mt = 0; mt < 2; mt++) {
#pragma unroll
        for (int nt = 0; nt < 8; nt++) {
            size_t row = m0 + wm + mt * 16 + (lane >> 2);
            int gcol = n0 + wn + nt * 8 + ((lane & 3) << 1);
            float2 lo = make_float2(acc[mt][nt][0], acc[mt][nt][1]);
            float2 hi = make_float2(acc[mt][nt][2], acc[mt][nt][3]);
            if (EPI == EPI_BIAS || EPI == EPI_BIAS_ELU) {
                float2 bb = *(const float2*)(bias + gcol);
                lo.x += bb.x; lo.y += bb.y;
                hi.x += bb.x; hi.y += bb.y;
            }
            if (EPI == EPI_BIAS_ELU) {
                lo.x = lo.x > 0.f ? lo.x : expm1f(lo.x);
                lo.y = lo.y > 0.f ? lo.y : expm1f(lo.y);
                hi.x = hi.x > 0.f ? hi.x : expm1f(hi.x);
                hi.y = hi.y > 0.f ? hi.y : expm1f(hi.y);
            }
            if (SPLIT3) {
                int col = gcol & 1023;
                *(__half2*)(Ch + row * 1024 + col)       = __floats2half2_rn(lo.x, lo.y);
                *(__half2*)(Ch + (row + 8) * 1024 + col) = __floats2half2_rn(hi.x, hi.y);
            } else if (sizeof(OutT) == 2) {
                *(__half2*)((__half*)C + row * N + gcol)       = __floats2half2_rn(lo.x, lo.y);
                *(__half2*)((__half*)C + (row + 8) * N + gcol) = __floats2half2_rn(hi.x, hi.y);
            } else {
                *(float2*)((float*)C + row * N + gcol)       = lo;
                *(float2*)((float*)C + (row + 8) * N + gcol) = hi;
            }
        }
    }
}

// ---------------- fused dd GEMM + Performer feature map -----------------------
// (unchanged — proven)
#define DS 72

template<int MODE>
__global__ __launch_bounds__(256, 2)
void ddexp(const __half* __restrict__ A, const __half* __restrict__ Bp,
           __half* __restrict__ outp, unsigned* __restrict__ gmax)
{
    __shared__ __align__(16) __half As[64 * DS];
    __shared__ __align__(16) __half Bs[256 * DS];
    __shared__ float sdiag[64];
    __shared__ float srmax[4][64];

    const int tid  = threadIdx.x;
    const int wid  = tid >> 5;
    const int lane = tid & 31;
    const int wm   = (wid >> 2) * 32;
    const int wn   = (wid & 3)  * 64;
    const size_t m0 = (size_t)blockIdx.x * 64;

#pragma unroll
    for (int i = 0; i < 2; i++) {
        int c = tid + i * 256;
        int r = c >> 3, cc = (c & 7) << 3;
        *(uint4*)&As[r * DS + cc] = *(const uint4*)(A + (m0 + r) * 64 + cc);
    }
#pragma unroll
    for (int i = 0; i < 8; i++) {
        int c = tid + i * 256;
        int r = c >> 3, cc = (c & 7) << 3;
        *(uint4*)&Bs[r * DS + cc] = *(const uint4*)(Bp + (size_t)r * 64 + cc);
    }
    __syncthreads();

    if (MODE != DD_KMAX && tid < 64) {
        const __half2* row = (const __half2*)&As[tid * DS];
        float ss = 0.f;
#pragma unroll
        for (int i = 0; i < 32; i++) {
            float2 v = __half22float2(row[i]);
            ss += v.x * v.x + v.y * v.y;
        }
        sdiag[tid] = ss;
    }

    const int matid = lane >> 3, rowin = lane & 7;
    const unsigned sA = (unsigned)__cvta_generic_to_shared(As);
    const unsigned sB = (unsigned)__cvta_generic_to_shared(Bs);
    unsigned aoff[2], boff[4];
#pragma unroll
    for (int mt = 0; mt < 2; mt++)
        aoff[mt] = sA + (unsigned)(((wm + mt * 16 + rowin + ((matid & 1) << 3)) * DS
                                    + ((matid & 2) << 2)) << 1);
#pragma unroll
    for (int p = 0; p < 4; p++)
        boff[p] = sB + (unsigned)(((wn + ((p << 1) + ((matid >> 1) & 1)) * 8 + rowin) * DS
                                    + ((matid & 1) << 3)) << 1);

    float acc[2][8][4];
#pragma unroll
    for (int mt = 0; mt < 2; mt++)
#pragma unroll
        for (int nt = 0; nt < 8; nt++)
#pragma unroll
            for (int i = 0; i < 4; i++) acc[mt][nt][i] = 0.f;

#pragma unroll
    for (int ks = 0; ks < 4; ks++) {
        const unsigned cb = (unsigned)(ks << 5);
        unsigned af[2][4], bf[4][4];
#pragma unroll
        for (int mt = 0; mt < 2; mt++) ldsm_x4(af[mt], aoff[mt] + cb);
#pragma unroll
        for (int p = 0; p < 4; p++)   ldsm_x4(bf[p],  boff[p]  + cb);
#pragma unroll
        for (int mt = 0; mt < 2; mt++)
#pragma unroll
            for (int p = 0; p < 4; p++) {
                mma_f16(acc[mt][2 * p],     af[mt], &bf[p][0]);
                mma_f16(acc[mt][2 * p + 1], af[mt], &bf[p][2]);
            }
    }

    if (MODE == DD_KMAX) {
        float mx = -3.4e38f;
#pragma unroll
        for (int mt = 0; mt < 2; mt++)
#pragma unroll
            for (int nt = 0; nt < 8; nt++)
#pragma unroll
                for (int i = 0; i < 4; i++) mx = fmaxf(mx, acc[mt][nt][i]);
#pragma unroll
        for (int o = 16; o; o >>= 1) mx = fmaxf(mx, __shfl_xor_sync(0xffffffffu, mx, o));
        if (lane == 0) {
            unsigned u = __float_as_uint(mx);
            u = (u & 0x80000000u) ? ~u : (u | 0x80000000u);
            atomicMax(gmax, u);
        }
        return;
    }

    if (MODE == DD_Q) {
#pragma unroll
        for (int mt = 0; mt < 2; mt++) {
            float m0v = -3.4e38f, m1v = -3.4e38f;
#pragma unroll
            for (int nt = 0; nt < 8; nt++) {
                m0v = fmaxf(m0v, fmaxf(acc[mt][nt][0], acc[mt][nt][1]));
                m1v = fmaxf(m1v, fmaxf(acc[mt][nt][2], acc[mt][nt][3]));
            }
#pragma unroll
            for (int o = 1; o <= 2; o <<= 1) {
                m0v = fmaxf(m0v, __shfl_xor_sync(0xffffffffu, m0v, o));
                m1v = fmaxf(m1v, __shfl_xor_sync(0xffffffffu, m1v, o));
            }
            if ((lane & 3) == 0) {
                srmax[wid & 3][wm + mt * 16 + (lane >> 2)]     = m0v;
                srmax[wid & 3][wm + mt * 16 + 8 + (lane >> 2)] = m1v;
            }
        }
    }
    __syncthreads();

    const float gm = (MODE == DD_KEXP) ? unflip(*gmax) : 0.f;
    const float L2E = 1.4426950408889634f;
    const __half2 eps2 = __float2half2_rn(1e-6f);
    const __half2 rat2 = __float2half2_rn(0.0625f);

#pragma unroll
    for (int mt = 0; mt < 2; mt++) {
        const int r0 = wm + mt * 16 + (lane >> 2);
        const int r1 = r0 + 8;
        float c0, c1;
        if (MODE == DD_Q) {
            float rm0 = fmaxf(fmaxf(srmax[0][r0], srmax[1][r0]),
                              fmaxf(srmax[2][r0], srmax[3][r0]));
            float rm1 = fmaxf(fmaxf(srmax[0][r1], srmax[1][r1]),
                              fmaxf(srmax[2][r1], srmax[3][r1]));
            c0 = 0.0625f * sdiag[r0] + rm0;
            c1 = 0.0625f * sdiag[r1] + rm1;
        } else {
            c0 = 0.0625f * sdiag[r0] + gm;
            c1 = 0.0625f * sdiag[r1] + gm;
        }
        const float c0l = c0 * L2E, c1l = c1 * L2E;
#pragma unroll
        for (int nt = 0; nt < 8; nt++) {
            const int col = wn + nt * 8 + ((lane & 3) << 1);
            __half2 t01 = __floats2half2_rn(fmaf(acc[mt][nt][0], L2E, -c0l),
                                            fmaf(acc[mt][nt][1], L2E, -c0l));
            __half2 t23 = __floats2half2_rn(fmaf(acc[mt][nt][2], L2E, -c1l),
                                            fmaf(acc[mt][nt][3], L2E, -c1l));
            __half2 e01 = __hmul2(__hadd2(h2ex2(t01), eps2), rat2);
            __half2 e23 = __hmul2(__hadd2(h2ex2(t23), eps2), rat2);
            *(__half2*)(outp + (m0 + r0) * 256 + col) = e01;
            *(__half2*)(outp + (m0 + r1) * 256 + col) = e23;
        }
    }
}

// ------------- fp16 batched strided GEMM over (b,h), optional split-K --------
// 3-stage cp.async pipeline, wait_group<1>, empty-commit tail fix.
#define BAS 136
#define NAS 40
#define BBS 72

template<bool TRANSA, bool DIV, typename OutT, int NSPLIT>
__global__ __launch_bounds__(256, 2)
void hgemm_bh(const __half* __restrict__ A, size_t sAb, size_t sAh, int lda,
              const __half* __restrict__ B, size_t sBb, size_t sBh, int ldb,
              OutT* __restrict__ C, size_t sCb, size_t sCh, int ldc, size_t sCsplit,
              const float* __restrict__ aux, size_t sXb, size_t sXh, int ldx,
              int M, int N, int K)
{
    constexpr int ABUFH = TRANSA ? (32 * BAS) : (128 * NAS);
    constexpr int BBUFH = 32 * BBS;
    __shared__ __align__(16) __half As[3 * ABUFH];
    __shared__ __align__(16) __half Bs[3 * BBUFH];

    const int z     = blockIdx.z;
    const int split = (NSPLIT > 1) ? (z >> 6) : 0;
    const int zz    = (NSPLIT > 1) ? (z & 63) : z;
    const int zb = zz >> 4, zh = zz & 15;
    const __half* Ab = A + (size_t)zb * sAb + (size_t)zh * sAh;
    const __half* Bb = B + (size_t)zb * sBb + (size_t)zh * sBh;
    OutT*         Cb = C + (size_t)zb * sCb + (size_t)zh * sCh
                         + (size_t)split * sCsplit;
    if (NSPLIT > 1) {
        Ab += (size_t)split * K * lda;
        Bb += (size_t)split * K * ldb;
    }

    const int tid  = threadIdx.x;
    const int wid  = tid >> 5;
    const int lane = tid & 31;
    const int wm   = (wid >> 1) * 32;
    const int wn   = (wid & 1)  * 32;
    const int m0   = blockIdx.y * 128;

    const int matid = lane >> 3, rowin = lane & 7;
    const unsigned sAs = (unsigned)__cvta_generic_to_shared(As);
    const unsigned sBs = (unsigned)__cvta_generic_to_shared(Bs);

    unsigned aoff[2], boff[2];
#pragma unroll
    for (int mt = 0; mt < 2; mt++) {
        if (TRANSA)
            aoff[mt] = sAs + (unsigned)(((rowin + ((matid >> 1) << 3)) * BAS
                                         + wm + mt * 16 + ((matid & 1) << 3)) << 1);
        else
            aoff[mt] = sAs + (unsigned)(((wm + mt * 16 + rowin + ((matid & 1) << 3)) * NAS
                                         + ((matid & 2) << 2)) << 1);
    }
#pragma unroll
    for (int p = 0; p < 2; p++)
        boff[p] = sBs + (unsigned)(((rowin + ((matid & 1) << 3)) * BBS
                                    + wn + (p << 4) + ((matid >> 1) << 3)) << 1);

    const int ta_kr = tid >> 4, ta_mc = (tid & 15) << 3;
    const int na_r0 = tid >> 2, na_k0 = (tid & 3) << 3;
    const int b_kr  = tid >> 3, b_nc  = (tid & 7) << 3;

    unsigned dA0, dA1, dB;
    if (TRANSA) {
        dA0 = sAs + (unsigned)((ta_kr * BAS + ta_mc) << 1);
        dA1 = sAs + (unsigned)(((ta_kr + 16) * BAS + ta_mc) << 1);
    } else {
        dA0 = sAs + (unsigned)((na_r0 * NAS + na_k0) << 1);
        dA1 = sAs + (unsigned)(((na_r0 + 64) * NAS + na_k0) << 1);
    }
    dB = sBs + (unsigned)((b_kr * BBS + b_nc) << 1);

    float acc[2][4][4];
#pragma unroll
    for (int mt = 0; mt < 2; mt++)
#pragma unroll
        for (int nt = 0; nt < 4; nt++)
#pragma unroll
            for (int i = 0; i < 4; i++) acc[mt][nt][i] = 0.f;

    const int iters = K >> 5;

    auto issue = [&](int s, int k0) {
        const unsigned sa = (unsigned)(s * (ABUFH * 2));
        const unsigned sb = (unsigned)(s * (BBUFH * 2));
        if (TRANSA) {
            cpa16(dA0 + sa, Ab + (size_t)(k0 + ta_kr)      * lda + m0 + ta_mc);
            cpa16(dA1 + sa, Ab + (size_t)(k0 + ta_kr + 16) * lda + m0 + ta_mc);
        } else {
            cpa16(dA0 + sa, Ab + (size_t)(m0 + na_r0)      * lda + k0 + na_k0);
            cpa16(dA1 + sa, Ab + (size_t)(m0 + na_r0 + 64) * lda + k0 + na_k0);
        }
        cpa16(dB + sb, Bb + (size_t)(k0 + b_kr) * ldb + b_nc);
        cpa_commit();
    };

    issue(0, 0);
    if (iters > 1) issue(1, 32); else cpa_commit();

    int s = 0, s2 = 2;
    for (int it = 0; it < iters; it++) {
        cpa_wait<1>();
        __syncthreads();

        const unsigned ab = (unsigned)(s * (ABUFH * 2));
        const unsigned bb = (unsigned)(s * (BBUFH * 2));
#pragma unroll
        for (int ks = 0; ks < 2; ks++) {
            const unsigned aks = TRANSA ? (unsigned)(ks * 16 * BAS * 2) : (unsigned)(ks << 5);
            const unsigned bks = (unsigned)(ks * 16 * BBS * 2);
            unsigned af[2][4], bf[2][4];
#pragma unroll
            for (int mt = 0; mt < 2; mt++) {
                if (TRANSA) ldsm_x4t(af[mt], aoff[mt] + ab + aks);
                else        ldsm_x4 (af[mt], aoff[mt] + ab + aks);
            }
#pragma unroll
            for (int p = 0; p < 2; p++) ldsm_x4t(bf[p], boff[p] + bb + bks);
#pragma unroll
            for (int mt = 0; mt < 2; mt++)
#pragma unroll
                for (int p = 0; p < 2; p++) {
                    mma_f16(acc[mt][2 * p],     af[mt], &bf[p][0]);
                    mma_f16(acc[mt][2 * p + 1], af[mt], &bf[p][2]);
                }
        }

        if (it + 2 < iters) {
            issue(s2, (it + 2) << 5);
            s2 = (s2 + 1 == 3) ? 0 : s2 + 1;
        } else {
            cpa_commit();   // empty group: exact wait accounting at tail
        }
        s = (s + 1 == 3) ? 0 : s + 1;
        __syncthreads();
    }

#pragma unroll
    for (int mt = 0; mt < 2; mt++) {
        int row = m0 + wm + mt * 16 + (lane >> 2);
        float dv0 = 1.f, dv1 = 1.f;
        if (DIV) {
            dv0 = 1.f / aux[(size_t)zb * sXb + (size_t)zh * sXh + (size_t)row * ldx];
            dv1 = 1.f / aux[(size_t)zb * sXb + (size_t)zh * sXh + (size_t)(row + 8) * ldx];
        }
#pragma unroll
        for (int nt = 0; nt < 4; nt++) {
            int col = wn + nt * 8 + ((lane & 3) << 1);
            float2 lo = make_float2(acc[mt][nt][0] * dv0, acc[mt][nt][1] * dv0);
            float2 hi = make_float2(acc[mt][nt][2] * dv1, acc[mt][nt][3] * dv1);
            if (sizeof(OutT) == 2) {
                *(__half2*)((__half*)Cb + (size_t)row * ldc + col)       = __floats2half2_rn(lo.x, lo.y);
                *(__half2*)((__half*)Cb + (size_t)(row + 8) * ldc + col) = __floats2half2_rn(hi.x, hi.y);
            } else {
                *(float2*)((float*)Cb + (size_t)row * ldc + col)       = lo;
                *(float2*)((float*)Cb + (size_t)(row + 8) * ldc + col) = hi;
            }
        }
    }
}

// ---------------- small helper kernels --------------------------------------
__global__ void k_half4(const float4* __restrict__ in, __half2* __restrict__ out,
                        int n4)
{
    int i = blockIdx.x * 256 + threadIdx.x;
    if (i < n4) {
        float4 v = in[i];
        out[2 * i]     = __floats2half2_rn(v.x, v.y);
        out[2 * i + 1] = __floats2half2_rn(v.z, v.w);
    }
}

__global__ void k_transH(const float* __restrict__ in, __half* __restrict__ out,
                         int K, int N)
{
    __shared__ float t[32][33];
    const int n0 = blockIdx.x * 32, k0 = blockIdx.y * 32;
#pragma unroll
    for (int i = 0; i < 4; i++) {
        int kk = threadIdx.y + i * 8;
        t[kk][threadIdx.x] = in[(size_t)(k0 + kk) * N + n0 + threadIdx.x];
    }
    __syncthreads();
#pragma unroll
    for (int i = 0; i < 4; i++) {
        int nn = threadIdx.y + i * 8;
        out[(size_t)(n0 + nn) * K + k0 + threadIdx.x] = __float2half(t[threadIdx.x][nn]);
    }
}

__global__ void k_projH(const float* __restrict__ proj, __half* __restrict__ ph)
{
    int i = blockIdx.x * 256 + threadIdx.x;
    if (i < MMF * DHH)
        ph[i] = __float2half(proj[i] * 0.35355339059327373f);
}

__global__ void k_kvred(const float4* __restrict__ part, __half2* __restrict__ kv)
{
    int i = blockIdx.x * 256 + threadIdx.x;
    if (i < KVN / 4) {
        float4 a = part[i];
        float4 b = part[i + KVN / 4];
        float4 c = part[i + 2 * (KVN / 4)];
        float4 d = part[i + 3 * (KVN / 4)];
        kv[2 * i]     = __floats2half2_rn(a.x + b.x + c.x + d.x, a.y + b.y + c.y + d.y);
        kv[2 * i + 1] = __floats2half2_rn(a.z + b.z + c.z + d.z, a.w + b.w + c.w + d.w);
    }
}

__global__ void k_ksum(const __half* __restrict__ kp, float* __restrict__ ksum)
{
    int z = blockIdx.y;
    int b = z >> 4, h = z & 15;
    int m = threadIdx.x;
    size_t base = (size_t)b * 16777216 + (size_t)h * 256 + m;
    float s = 0.f;
    int l0 = blockIdx.x * 512;
    for (int l = l0; l < l0 + 512; l++) s += __half2float(kp[base + (size_t)l * 4096]);
    atomicAdd(&ksum[z * 256 + m], s);
}

__global__ void k_denom(const __half* __restrict__ qp, const float* __restrict__ ksum,
                        float* __restrict__ den)
{
    size_t w   = ((size_t)blockIdx.x * blockDim.x + threadIdx.x) >> 5;
    int   lane = threadIdx.x & 31;
    int   b    = (int)(w >> 16);
    int   h    = (int)(w & 15);
    const __half2* row = (const __half2*)(qp + w * 256);
    const float4*  ks  = (const float4*)(ksum + ((size_t)b * 16 + h) * 256);
    float4 k0 = ks[lane * 2], k1 = ks[lane * 2 + 1];
    float2 a0 = __half22float2(row[lane * 4]);
    float2 a1 = __half22float2(row[lane * 4 + 1]);
    float2 a2 = __half22float2(row[lane * 4 + 2]);
    float2 a3 = __half22float2(row[lane * 4 + 3]);
    float s = a0.x * k0.x + a0.y * k0.y + a1.x * k0.z + a1.y * k0.w
            + a2.x * k1.x + a2.y * k1.y + a3.x * k1.z + a3.y * k1.w;
#pragma unroll
    for (int o = 16; o; o >>= 1) s += __shfl_xor_sync(0xffffffffu, s, o);
    if (lane == 0) den[w] = s;
}

template<bool WRITE_H>
__global__ void k_ln(const float* __restrict__ a, const float* __restrict__ r,
                     const float* __restrict__ g, const float* __restrict__ b,
                     float* __restrict__ out, __half* __restrict__ outh)
{
    const int row = blockIdx.x;
    const int t   = threadIdx.x;
    const size_t base = (size_t)row * 1024;
    float4 xa = *(const float4*)(a + base + t * 4);
    float4 xr = *(const float4*)(r + base + t * 4);
    float4 s  = make_float4(xa.x + xr.x, xa.y + xr.y, xa.z + xr.z, xa.w + xr.w);
    float sum = s.x + s.y + s.z + s.w;
    float sq  = s.x * s.x + s.y * s.y + s.z * s.z + s.w * s.w;
#pragma unroll
    for (int o = 16; o; o >>= 1) {
        sum += __shfl_xor_sync(0xffffffffu, sum, o);
        sq  += __shfl_xor_sync(0xffffffffu, sq,  o);
    }
    __shared__ float ssum[8], ssq[8];
    __shared__ float s_mu, s_inv;
    int w = t >> 5;
    if ((t & 31) == 0) { ssum[w] = sum; ssq[w] = sq; }
    __syncthreads();
    if (t == 0) {
        float ts = 0.f, tq = 0.f;
        for (int i = 0; i < 8; i++) { ts += ssum[i]; tq += ssq[i]; }
        float mu  = ts * (1.f / 1024.f);
        float var = tq * (1.f / 1024.f) - mu * mu;
        s_mu = mu;
        s_inv = rsqrtf(var + 1e-6f);
    }
    __syncthreads();
    float mu = s_mu, inv = s_inv;
    float4 gg = *(const float4*)(g + t * 4);
    float4 bb = *(const float4*)(b + t * 4);
    float4 o = make_float4((s.x - mu) * inv * gg.x + bb.x,
                           (s.y - mu) * inv * gg.y + bb.y,
                           (s.z - mu) * inv * gg.z + bb.z,
                           (s.w - mu) * inv * gg.w + bb.w);
    *(float4*)(out + base + t * 4) = o;
    if (WRITE_H) {
        __half2* oh = (__half2*)(outh + base + t * 4);
        oh[0] = __floats2half2_rn(o.x, o.y);
        oh[1] = __floats2half2_rn(o.z, o.w);
    }
}

// ---------------- driver -----------------------------------------------------
extern "C" void kernel_launch(void* const* d_in, const int* in_sizes, int n_in,
                              void* d_out, int out_size)
{
    const float* x    = (const float*)d_in[0];
    const float* wq   = (const float*)d_in[1];
    const float* wk   = (const float*)d_in[2];
    const float* wv   = (const float*)d_in[3];
    const float* wo   = (const float*)d_in[4];
    const float* proj = (const float*)d_in[5];
    const float* ln1g = (const float*)d_in[6];
    const float* ln1b = (const float*)d_in[7];
    const float* ln2g = (const float*)d_in[8];
    const float* ln2b = (const float*)d_in[9];
    const float* w1   = (const float*)d_in[10];
    const float* b1   = (const float*)d_in[11];
    const float* w2   = (const float*)d_in[12];
    const float* b2   = (const float*)d_in[13];
    float* out = (float*)d_out;

    float *p_kvp, *p_ksum, *p_den, *p_tmp, *p_out1;
    __half *p_xh, *p_qh, *p_kh, *p_vh, *p_qph, *p_kph, *p_kvh;
    __half *p_out1h, *p_attnh, *p_hh, *p_projh;
    __half *p_wqkvT, *p_woT, *p_w1T, *p_w2T;
    unsigned* p_kmax;
    cudaGetSymbolAddress((void**)&p_kvp,   g_kvp);
    cudaGetSymbolAddress((void**)&p_ksum,  g_ksum);
    cudaGetSymbolAddress((void**)&p_den,   g_den);
    cudaGetSymbolAddress((void**)&p_tmp,   g_tmp);
    cudaGetSymbolAddress((void**)&p_out1,  g_out1);
    cudaGetSymbolAddress((void**)&p_kmax,  g_kmax);
    cudaGetSymbolAddress((void**)&p_xh,    g_xh);
    cudaGetSymbolAddress((void**)&p_qh,    g_qh);
    cudaGetSymbolAddress((void**)&p_kh,    g_kh);
    cudaGetSymbolAddress((void**)&p_vh,    g_vh);
    cudaGetSymbolAddress((void**)&p_qph,   g_qph);
    cudaGetSymbolAddress((void**)&p_kph,   g_kph);
    cudaGetSymbolAddress((void**)&p_kvh,   g_kvh);
    cudaGetSymbolAddress((void**)&p_out1h, g_out1h);
    cudaGetSymbolAddress((void**)&p_attnh, g_attnh);
    cudaGetSymbolAddress((void**)&p_hh,    g_hh);
    cudaGetSymbolAddress((void**)&p_projh, g_projh);
    cudaGetSymbolAddress((void**)&p_wqkvT, g_wqkvT);
    cudaGetSymbolAddress((void**)&p_woT,   g_woT);
    cudaGetSymbolAddress((void**)&p_w1T,   g_w1T);
    cudaGetSymbolAddress((void**)&p_w2T,   g_w2T);

    // allow 80KB dynamic smem for the 4 hgemm instantiations
    cudaFuncSetAttribute(hgemm<EPI_NONE, __half, true >, cudaFuncAttributeMaxDynamicSharedMemorySize, T5SMEM);
    cudaFuncSetAttribute(hgemm<EPI_NONE, float,  false>, cudaFuncAttributeMaxDynamicSharedMemorySize, T5SMEM);
    cudaFuncSetAttribute(hgemm<EPI_BIAS_ELU, __half, false>, cudaFuncAttributeMaxDynamicSharedMemorySize, T5SMEM);
    cudaFuncSetAttribute(hgemm<EPI_BIAS, float, false>, cudaFuncAttributeMaxDynamicSharedMemorySize, T5SMEM);

    // prep: x->fp16, pack transposed qkv weights into one [3072][1024] buffer
    k_half4<<<(NT * DD / 4 + 255) / 256, 256>>>((const float4*)x, (__half2*)p_xh, NT * DD / 4);
    k_transH<<<dim3(32, 32), dim3(32, 8)>>>(wq, p_wqkvT,               DD, DD);
    k_transH<<<dim3(32, 32), dim3(32, 8)>>>(wk, p_wqkvT + DD * DD,     DD, DD);
    k_transH<<<dim3(32, 32), dim3(32, 8)>>>(wv, p_wqkvT + 2 * DD * DD, DD, DD);
    k_projH<<<64, 256>>>(proj, p_projh);

    // merged QKV: one launch, slice-routed epilogue
    hgemm<EPI_NONE, __half, true><<<dim3(24, 128), 256, T5SMEM>>>(
        p_xh, p_wqkvT, nullptr, p_qh, p_kh, p_vh, NT, 3072, 1024);

    // remaining prep
    k_transH<<<dim3(32, 32),  dim3(32, 8)>>>(wo, p_woT, DD, DD);
    k_transH<<<dim3(128, 32), dim3(32, 8)>>>(w1, p_w1T, DD, DFF);
    k_transH<<<dim3(32, 128), dim3(32, 8)>>>(w2, p_w2T, DFF, DD);

    cudaMemsetAsync(p_kmax, 0, 4);
    cudaMemsetAsync(p_ksum, 0, BB * HH * MMF * sizeof(float));

    // fused dd + feature maps
    ddexp<DD_Q>   <<<NR / 64, 256>>>(p_qh, p_projh, p_qph, nullptr);
    ddexp<DD_KMAX><<<NR / 64, 256>>>(p_kh, p_projh, nullptr, p_kmax);
    ddexp<DD_KEXP><<<NR / 64, 256>>>(p_kh, p_projh, p_kph, p_kmax);

    // kv partials: fp16 split-K=4 over K=4096 (each 1024)
    hgemm_bh<true, false, float, 4><<<dim3(1, 2, 256), 256>>>(
        p_kph, (size_t)16777216, (size_t)256, 4096,
        p_vh,  (size_t)4194304,  (size_t)64,  1024,
        p_kvp, (size_t)(16 * 16384), (size_t)16384, 64, (size_t)KVN,
        nullptr, 0, 0, 0,
        256, 64, 1024);
    k_kvred<<<(KVN / 4 + 255) / 256, 256>>>((const float4*)p_kvp, (__half2*)p_kvh);

    k_ksum<<<dim3(8, 64), 256>>>(p_kph, p_ksum);
    k_denom<<<NR / 8, 256>>>(p_qph, p_ksum, p_den);

    // attn = (qp @ kv) / denom : fp16 -> fp16
    hgemm_bh<false, true, __half, 1><<<dim3(1, 32, 64), 256>>>(
        p_qph, (size_t)16777216, (size_t)256, 4096,
        p_kvh, (size_t)(16 * 16384), (size_t)16384, 64,
        p_attnh, (size_t)4194304, (size_t)64, 1024, (size_t)0,
        p_den,  (size_t)65536,   (size_t)1,  16,
        4096, 64, 256);

    // attn_out = attn @ wo^T -> fp32 tmp
    hgemm<EPI_NONE, float, false><<<dim3(8, 128), 256, T5SMEM>>>(
        p_attnh, p_woT, nullptr, p_tmp, nullptr, nullptr, NT, 1024, 1024);

    // out1 = LN(x + attn_out) -> fp32 + fp16
    k_ln<true><<<NT, 256>>>(p_tmp, x, ln1g, ln1b, p_out1, p_out1h);

    // FFN
    hgemm<EPI_BIAS_ELU, __half, false><<<dim3(32, 128), 256, T5SMEM>>>(
        p_out1h, p_w1T, b1, p_hh, nullptr, nullptr, NT, DFF, 1024);
    hgemm<EPI_BIAS, float, false><<<dim3(8, 128), 256, T5SMEM>>>(
        p_hh, p_w2T, b2, p_tmp, nullptr, nullptr, NT, 1024, DFF);

    // out2 = LN(out1 + ffn)
    k_ln<false><<<NT, 256>>>(p_tmp, p_out1, ln2g, ln2b, out, nullptr);
}